// round 4
// baseline (speedup 1.0000x reference)
#include <cuda_runtime.h>
#include <cuda_bf16.h>
#include <cstdint>

// Problem constants
static constexpr int BB  = 8192;   // batch
static constexpr int DK  = 1024;   // embedding dim
static constexpr int NT  = 64;     // 8192 / 128 tiles per side
static constexpr int NCH = 16;     // 1024 / 64 K-chunks
static constexpr float HNW_SCALE = 1.5f;   // 1 + hard_negative_weight
// 1/T = 20 is folded into the S-side bf16 convert (20 is exact in bf16).

static constexpr int STAGE_BYTES = 32768;            // A(16K) + B(16K) bf16
static constexpr int TILE_PAD    = 129;              // fp32 tile row pad (conflict-free)
static constexpr int SMEM_BYTES  = 3 * STAGE_BYTES;  // 98304 >= 128*129*4 (66048); 2 CTAs/SM

// ------------------------- device scratch (static, no allocs) -------------------------
__device__ __align__(256) __nv_bfloat16 g_Ibf[(size_t)BB * DK];
__device__ __align__(256) __nv_bfloat16 g_Sbf[(size_t)BB * DK];
__device__ float g_rowMax[NT * BB];
__device__ float g_rowSum[NT * BB];
__device__ float g_rowHn [NT * BB];
__device__ float g_colMax[NT * BB];
__device__ float g_colSum[NT * BB];
__device__ float g_colHn [NT * BB];
__device__ float g_diag  [BB];
__device__ float g_part  [64];

// ------------------------- helpers -------------------------
static __device__ __forceinline__ uint32_t smem_u32(const void* p) {
    uint32_t a;
    asm("{ .reg .u64 t; cvta.to.shared.u64 t, %1; cvt.u32.u64 %0, t; }" : "=r"(a) : "l"(p));
    return a;
}
static __device__ __forceinline__ void cp16(uint32_t s, const void* g) {
    asm volatile("cp.async.cg.shared.global [%0], [%1], 16;" :: "r"(s), "l"(g) : "memory");
}
// Swizzled smem addr for a [128][64-bf16] tile, 128B/row, 16B chunks xor'd by row&7
static __device__ __forceinline__ uint32_t sw_addr(uint32_t base, int row, int kchunk) {
    return base + (uint32_t)(row * 128) + (uint32_t)(((kchunk ^ (row & 7)) << 4));
}
static __device__ __forceinline__ void ldsm_x4(uint32_t& r0, uint32_t& r1, uint32_t& r2,
                                               uint32_t& r3, uint32_t addr) {
    asm volatile("ldmatrix.sync.aligned.m8n8.x4.shared.b16 {%0,%1,%2,%3}, [%4];"
                 : "=r"(r0), "=r"(r1), "=r"(r2), "=r"(r3) : "r"(addr));
}
static __device__ __forceinline__ void mma16816(float& c0, float& c1, float& c2, float& c3,
                                                uint32_t a0, uint32_t a1, uint32_t a2,
                                                uint32_t a3, uint32_t b0, uint32_t b1) {
    asm volatile(
        "mma.sync.aligned.m16n8k16.row.col.f32.bf16.bf16.f32 "
        "{%0,%1,%2,%3}, {%4,%5,%6,%7}, {%8,%9}, {%0,%1,%2,%3};"
        : "+f"(c0), "+f"(c1), "+f"(c2), "+f"(c3)
        : "r"(a0), "r"(a1), "r"(a2), "r"(a3), "r"(b0), "r"(b1));
}

// ------------------------- kernel 1: fp32 -> bf16 convert -------------------------
// S side is pre-scaled by 1/T = 20 (exact in bf16 exponent/mantissa terms).
__global__ void convert_kernel(const float* __restrict__ I, const float* __restrict__ S) {
    const uint32_t n4 = (uint32_t)(BB * DK) / 4u;  // 2,097,152 float4 per matrix
    uint32_t i = blockIdx.x * blockDim.x + threadIdx.x;
    const float4* src;
    __nv_bfloat16* dst;
    uint32_t j;
    float sc;
    if (i < n4) { src = (const float4*)I; dst = g_Ibf; j = i; sc = 1.0f; }
    else        { src = (const float4*)S; dst = g_Sbf; j = i - n4; sc = 20.0f; }
    float4 v = src[j];
    __nv_bfloat162 h0, h1;
    h0.x = __float2bfloat16(v.x * sc); h0.y = __float2bfloat16(v.y * sc);
    h1.x = __float2bfloat16(v.z * sc); h1.y = __float2bfloat16(v.w * sc);
    ((__nv_bfloat162*)dst)[2 * j]     = h0;
    ((__nv_bfloat162*)dst)[2 * j + 1] = h1;
}

// ------------------------- kernel 2: GEMM tile + fused reductions -------------------------
// 256 threads, warp grid 4(M) x 2(N); warp tile 32x64; mma m16n8k16. 2 CTAs/SM.
static __device__ __forceinline__ void load_chunk(int tid, const __nv_bfloat16* Ap,
                                                  const __nv_bfloat16* Bp,
                                                  uint32_t DATA, int kc) {
    int s = kc % 3;
    uint32_t abase = DATA + (uint32_t)s * STAGE_BYTES;
    uint32_t bbase = abase + 16384u;
    const __nv_bfloat16* ga0 = Ap + kc * 64;
    const __nv_bfloat16* gb0 = Bp + kc * 64;
#pragma unroll
    for (int i = 0; i < 4; i++) {
        int v = tid + i * 256;
        int row = v >> 3, cv = v & 7;
        cp16(sw_addr(abase, row, cv), ga0 + (size_t)row * DK + cv * 8);
        cp16(sw_addr(bbase, row, cv), gb0 + (size_t)row * DK + cv * 8);
    }
}

__global__ void __launch_bounds__(256, 2) gemm_kernel() {
    extern __shared__ char smem[];
    const uint32_t DATA = smem_u32(smem);
    const int tid = threadIdx.x, wid = tid >> 5, lane = tid & 31;
    const int wm = wid >> 1, wn = wid & 1;   // 4 x 2 warp grid
    const int bx = blockIdx.x, by = blockIdx.y;

    const __nv_bfloat16* Ap = g_Ibf + (size_t)by * 128 * DK;
    const __nv_bfloat16* Bp = g_Sbf + (size_t)bx * 128 * DK;

    float acc[2][8][4];
#pragma unroll
    for (int mt = 0; mt < 2; mt++)
#pragma unroll
        for (int nt = 0; nt < 8; nt++)
#pragma unroll
            for (int q = 0; q < 4; q++) acc[mt][nt][q] = 0.f;

    // prologue: 3 stages in flight
    load_chunk(tid, Ap, Bp, DATA, 0);
    asm volatile("cp.async.commit_group;" ::: "memory");
    load_chunk(tid, Ap, Bp, DATA, 1);
    asm volatile("cp.async.commit_group;" ::: "memory");
    load_chunk(tid, Ap, Bp, DATA, 2);
    asm volatile("cp.async.commit_group;" ::: "memory");

    for (int k = 0; k < NCH; k++) {
        asm volatile("cp.async.wait_group 2;" ::: "memory");
        __syncthreads();
        int s = k % 3;
        uint32_t abase = DATA + (uint32_t)s * STAGE_BYTES;
        uint32_t bbase = abase + 16384u;
#pragma unroll
        for (int kk = 0; kk < 4; kk++) {
            // A fragments: two m16 tiles
            uint32_t a[2][4];
#pragma unroll
            for (int mt = 0; mt < 2; mt++) {
                int row = wm * 32 + mt * 16 + (lane & 15);
                int kch = 2 * kk + (lane >> 4);
                ldsm_x4(a[mt][0], a[mt][1], a[mt][2], a[mt][3], sw_addr(abase, row, kch));
            }
            // B fragments: 8 n8 tiles via 4 x4-ldmatrix (2 tiles each)
            uint32_t b[8][2];
#pragma unroll
            for (int np = 0; np < 4; np++) {
                int nrow = wn * 64 + np * 16 + (lane & 7) + ((lane >> 4) << 3);
                int kch = 2 * kk + ((lane >> 3) & 1);
                uint32_t r0, r1, r2, r3;
                ldsm_x4(r0, r1, r2, r3, sw_addr(bbase, nrow, kch));
                b[2 * np][0] = r0; b[2 * np][1] = r1;
                b[2 * np + 1][0] = r2; b[2 * np + 1][1] = r3;
            }
#pragma unroll
            for (int mt = 0; mt < 2; mt++)
#pragma unroll
                for (int nt = 0; nt < 8; nt++)
                    mma16816(acc[mt][nt][0], acc[mt][nt][1], acc[mt][nt][2], acc[mt][nt][3],
                             a[mt][0], a[mt][1], a[mt][2], a[mt][3], b[nt][0], b[nt][1]);
        }
        __syncthreads();
        if (k + 3 < NCH) load_chunk(tid, Ap, Bp, DATA, k + 3);
        asm volatile("cp.async.commit_group;" ::: "memory");  // empty groups keep accounting uniform
    }
    asm volatile("cp.async.wait_group 0;" ::: "memory");
    __syncthreads();   // all warps done with pipeline smem -> reuse as fp32 tile

    // scatter accum -> smem fp32 tile (already scaled by 1/T via S-side convert)
    float* tile = (float*)smem;
    {
        const int r0 = wm * 32 + (lane >> 2);
        const int c0base = wn * 64 + 2 * (lane & 3);
#pragma unroll
        for (int mt = 0; mt < 2; mt++) {
#pragma unroll
            for (int nt = 0; nt < 8; nt++) {
                int r = r0 + mt * 16;
                int c = c0base + nt * 8;
                tile[r * TILE_PAD + c]           = acc[mt][nt][0];
                tile[r * TILE_PAD + c + 1]       = acc[mt][nt][1];
                tile[(r + 8) * TILE_PAD + c]     = acc[mt][nt][2];
                tile[(r + 8) * TILE_PAD + c + 1] = acc[mt][nt][3];
            }
        }
    }
    __syncthreads();

    const bool dT = (bx == by);
    if (tid < 128) {   // row-side partials (one thread per row)
        int t = tid;
        float m = -3.4e38f, h = -3.4e38f;
#pragma unroll 8
        for (int c = 0; c < 128; c++) {
            float x = tile[t * TILE_PAD + c];
            m = fmaxf(m, x);
            if (!(dT && c == t)) h = fmaxf(h, x);
        }
        float ssum = 0.f;
#pragma unroll 8
        for (int c = 0; c < 128; c++) ssum += __expf(tile[t * TILE_PAD + c] - m);
        int rg = by * 128 + t;
        g_rowMax[bx * BB + rg] = m;
        g_rowSum[bx * BB + rg] = ssum;
        g_rowHn [bx * BB + rg] = h;
        if (dT) g_diag[rg] = tile[t * TILE_PAD + t];
    } else {           // col-side partials (one thread per col)
        int t = tid - 128;
        float m = -3.4e38f, h = -3.4e38f;
#pragma unroll 8
        for (int rr = 0; rr < 128; rr++) {
            float x = tile[rr * TILE_PAD + t];
            m = fmaxf(m, x);
            if (!(dT && rr == t)) h = fmaxf(h, x);
        }
        float ssum = 0.f;
#pragma unroll 8
        for (int rr = 0; rr < 128; rr++) ssum += __expf(tile[rr * TILE_PAD + t] - m);
        int cg = bx * 128 + t;
        g_colMax[by * BB + cg] = m;
        g_colSum[by * BB + cg] = ssum;
        g_colHn [by * BB + cg] = h;
    }
}

// ------------------------- kernel 3: merge partials -> per-row/col loss + block sums ---------
__global__ void combine_kernel() {
    int i = blockIdx.x * blockDim.x + threadIdx.x;  // 0 .. 2*BB-1
    int idx = i & (BB - 1);
    const float *PM, *PS, *PH;
    if (i < BB) { PM = g_rowMax; PS = g_rowSum; PH = g_rowHn; }
    else        { PM = g_colMax; PS = g_colSum; PH = g_colHn; }

    float m = -3.4e38f, h = -3.4e38f;
#pragma unroll 8
    for (int t = 0; t < NT; t++) {
        m = fmaxf(m, PM[t * BB + idx]);
        h = fmaxf(h, PH[t * BB + idx]);
    }
    float s = 0.f;
#pragma unroll 8
    for (int t = 0; t < NT; t++)
        s += PS[t * BB + idx] * __expf(PM[t * BB + idx] - m);

    float d = g_diag[idx];
    float loss;
    if (h > 0.f) {
        // hard negative is the off-diag max; scale it by 1.5
        float M = fmaxf(m, HNW_SCALE * h);
        float S = s * __expf(m - M) - __expf(h - M) + __expf(HNW_SCALE * h - M);
        loss = M + __logf(S) - d;
    } else {
        // masked argmax lands on the zeroed diagonal -> diagonal gets scaled (matches ref)
        float dd = HNW_SCALE * d;
        float snd = s - __expf(d - m);
        float M = fmaxf(h, dd);
        float S = snd * __expf(m - M) + __expf(dd - M);
        loss = M + __logf(S) - dd;
    }

    // block-level deterministic partial sum
    __shared__ float red[256];
    red[threadIdx.x] = loss;
    __syncthreads();
    for (int o = 128; o > 0; o >>= 1) {
        if (threadIdx.x < (unsigned)o) red[threadIdx.x] += red[threadIdx.x + o];
        __syncthreads();
    }
    if (threadIdx.x == 0) g_part[blockIdx.x] = red[0];
}

// ------------------------- kernel 4: tiny deterministic reduction -------------------------
__global__ void finalize_kernel(float* out) {
    __shared__ float red[64];
    if (threadIdx.x < 64) red[threadIdx.x] = g_part[threadIdx.x];
    __syncthreads();
    if (threadIdx.x == 0) {
        float s = 0.f;
#pragma unroll
        for (int i = 0; i < 64; i++) s += red[i];
        out[0] = s / (float)(2 * BB);
    }
}

// ------------------------- launch -------------------------
extern "C" void kernel_launch(void* const* d_in, const int* in_sizes, int n_in,
                              void* d_out, int out_size) {
    const float* I = (const float*)d_in[0];
    const float* S = (const float*)d_in[1];
    float* out = (float*)d_out;

    cudaFuncSetAttribute(gemm_kernel, cudaFuncAttributeMaxDynamicSharedMemorySize, SMEM_BYTES);

    convert_kernel<<<16384, 256>>>(I, S);
    gemm_kernel<<<dim3(NT, NT, 1), 256, SMEM_BYTES>>>();
    combine_kernel<<<(2 * BB) / 256, 256>>>();
    finalize_kernel<<<1, 64>>>(out);
}

// round 5
// speedup vs baseline: 1.5728x; 1.5728x over previous
#include <cuda_runtime.h>
#include <cuda_bf16.h>
#include <cstdint>

// Problem constants
static constexpr int BB  = 8192;   // batch
static constexpr int DK  = 1024;   // embedding dim
static constexpr int NT  = 64;     // 8192 / 128 tiles per side
static constexpr int NCH = 8;      // 1024 / 128 K-chunks (int8: BK=128)
static constexpr float HNW_SCALE = 1.5f;   // 1 + hard_negative_weight

static constexpr int STAGE_BYTES = 32768;            // A(16K) + B(16K) int8
static constexpr int TILE_PAD    = 129;              // fp32 tile row pad (conflict-free)
static constexpr int SMEM_BYTES  = 3 * STAGE_BYTES;  // 98304 >= 128*129*4 (66048)

// ------------------------- device scratch (static, no allocs) -------------------------
__device__ __align__(256) int8_t g_Iq[(size_t)BB * DK];
__device__ __align__(256) int8_t g_Sq[(size_t)BB * DK];
__device__ float g_qsI[BB];        // rowmax/127
__device__ float g_qsS[BB];        // rowmax/127 * 20  (1/T folded here)
__device__ float g_rowMax[NT * BB];
__device__ float g_rowSum[NT * BB];
__device__ float g_rowHn [NT * BB];
__device__ float g_colMax[NT * BB];
__device__ float g_colSum[NT * BB];
__device__ float g_colHn [NT * BB];
__device__ float g_diag  [BB];
__device__ float g_part  [64];

// ------------------------- helpers -------------------------
static __device__ __forceinline__ uint32_t smem_u32(const void* p) {
    uint32_t a;
    asm("{ .reg .u64 t; cvta.to.shared.u64 t, %1; cvt.u32.u64 %0, t; }" : "=r"(a) : "l"(p));
    return a;
}
static __device__ __forceinline__ void cp16(uint32_t s, const void* g) {
    asm volatile("cp.async.cg.shared.global [%0], [%1], 16;" :: "r"(s), "l"(g) : "memory");
}
// Swizzled smem addr for a [128 rows][128 B] tile; 16B chunks xor'd by row&7
static __device__ __forceinline__ uint32_t sw_addr(uint32_t base, int row, int kchunk) {
    return base + (uint32_t)(row * 128) + (uint32_t)(((kchunk ^ (row & 7)) << 4));
}
static __device__ __forceinline__ void ldsm_x4(uint32_t& r0, uint32_t& r1, uint32_t& r2,
                                               uint32_t& r3, uint32_t addr) {
    asm volatile("ldmatrix.sync.aligned.m8n8.x4.shared.b16 {%0,%1,%2,%3}, [%4];"
                 : "=r"(r0), "=r"(r1), "=r"(r2), "=r"(r3) : "r"(addr));
}
static __device__ __forceinline__ void imma16832(int& c0, int& c1, int& c2, int& c3,
                                                 uint32_t a0, uint32_t a1, uint32_t a2,
                                                 uint32_t a3, uint32_t b0, uint32_t b1) {
    asm volatile(
        "mma.sync.aligned.m16n8k32.row.col.s32.s8.s8.s32 "
        "{%0,%1,%2,%3}, {%4,%5,%6,%7}, {%8,%9}, {%0,%1,%2,%3};"
        : "+r"(c0), "+r"(c1), "+r"(c2), "+r"(c3)
        : "r"(a0), "r"(a1), "r"(a2), "r"(a3), "r"(b0), "r"(b1));
}

// ------------------------- kernel 1: fp32 -> int8 per-row symmetric quant ----------------
// One block per row (16384 blocks). scale_S additionally folds 1/T = 20.
__global__ void __launch_bounds__(256) quant_kernel(const float* __restrict__ I,
                                                    const float* __restrict__ S) {
    const int row = blockIdx.x;
    const bool isI = row < BB;
    const int r = isI ? row : row - BB;
    const float* src = (isI ? I : S) + (size_t)r * DK;
    const int tid = threadIdx.x;

    float4 v = ((const float4*)src)[tid];
    float m = fmaxf(fmaxf(fabsf(v.x), fabsf(v.y)), fmaxf(fabsf(v.z), fabsf(v.w)));
    __shared__ float red[8];
#pragma unroll
    for (int o = 16; o; o >>= 1) m = fmaxf(m, __shfl_xor_sync(~0u, m, o));
    if ((tid & 31) == 0) red[tid >> 5] = m;
    __syncthreads();
    if (tid < 8) {
        float t = red[tid];
#pragma unroll
        for (int o = 4; o; o >>= 1) t = fmaxf(t, __shfl_xor_sync(0xffu, t, o));
        if (tid == 0) red[0] = t;
    }
    __syncthreads();
    m = fmaxf(red[0], 1e-20f);
    const float inv = 127.0f / m;
    char4 q;
    q.x = (char)__float2int_rn(v.x * inv);
    q.y = (char)__float2int_rn(v.y * inv);
    q.z = (char)__float2int_rn(v.z * inv);
    q.w = (char)__float2int_rn(v.w * inv);
    ((char4*)(isI ? g_Iq : g_Sq))[(size_t)r * 256 + tid] = q;
    if (tid == 0) {
        if (isI) g_qsI[r] = m / 127.0f;
        else     g_qsS[r] = (m / 127.0f) * 20.0f;
    }
}

// ------------------------- kernel 2: int8 GEMM tile + fused reductions -------------------
// 256 threads, warp grid 4(M) x 2(N); warp tile 32x64; mma m16n8k32.s8.
static __device__ __forceinline__ void load_chunk(int tid, const int8_t* Ap,
                                                  const int8_t* Bp,
                                                  uint32_t DATA, int kc) {
    int s = kc % 3;
    uint32_t abase = DATA + (uint32_t)s * STAGE_BYTES;
    uint32_t bbase = abase + 16384u;
    const int8_t* ga0 = Ap + kc * 128;
    const int8_t* gb0 = Bp + kc * 128;
#pragma unroll
    for (int i = 0; i < 4; i++) {
        int v = tid + i * 256;
        int row = v >> 3, cv = v & 7;
        cp16(sw_addr(abase, row, cv), ga0 + (size_t)row * DK + cv * 16);
        cp16(sw_addr(bbase, row, cv), gb0 + (size_t)row * DK + cv * 16);
    }
}

__global__ void __launch_bounds__(256, 2) gemm_kernel() {
    extern __shared__ char smem[];
    const uint32_t DATA = smem_u32(smem);
    const int tid = threadIdx.x, wid = tid >> 5, lane = tid & 31;
    const int wm = wid >> 1, wn = wid & 1;   // 4 x 2 warp grid
    const int bx = blockIdx.x, by = blockIdx.y;

    const int8_t* Ap = g_Iq + (size_t)by * 128 * DK;
    const int8_t* Bp = g_Sq + (size_t)bx * 128 * DK;

    int acc[2][8][4];
#pragma unroll
    for (int mt = 0; mt < 2; mt++)
#pragma unroll
        for (int nt = 0; nt < 8; nt++)
#pragma unroll
            for (int q = 0; q < 4; q++) acc[mt][nt][q] = 0;

    // prologue: 3 stages in flight
    load_chunk(tid, Ap, Bp, DATA, 0);
    asm volatile("cp.async.commit_group;" ::: "memory");
    load_chunk(tid, Ap, Bp, DATA, 1);
    asm volatile("cp.async.commit_group;" ::: "memory");
    load_chunk(tid, Ap, Bp, DATA, 2);
    asm volatile("cp.async.commit_group;" ::: "memory");

    for (int k = 0; k < NCH; k++) {
        asm volatile("cp.async.wait_group 2;" ::: "memory");
        __syncthreads();
        int s = k % 3;
        uint32_t abase = DATA + (uint32_t)s * STAGE_BYTES;
        uint32_t bbase = abase + 16384u;
#pragma unroll
        for (int kk = 0; kk < 4; kk++) {   // 4 x K=32 per 128B chunk-row
            // A fragments: two m16 tiles (16B chunk pairs)
            uint32_t a[2][4];
#pragma unroll
            for (int mt = 0; mt < 2; mt++) {
                int row = wm * 32 + mt * 16 + (lane & 15);
                int kch = 2 * kk + (lane >> 4);
                ldsm_x4(a[mt][0], a[mt][1], a[mt][2], a[mt][3], sw_addr(abase, row, kch));
            }
            // B fragments: 8 n8 tiles via 4 x4-ldmatrix (2 tiles each)
            uint32_t b[8][2];
#pragma unroll
            for (int np = 0; np < 4; np++) {
                int nrow = wn * 64 + np * 16 + (lane & 7) + ((lane >> 4) << 3);
                int kch = 2 * kk + ((lane >> 3) & 1);
                uint32_t r0, r1, r2, r3;
                ldsm_x4(r0, r1, r2, r3, sw_addr(bbase, nrow, kch));
                b[2 * np][0] = r0; b[2 * np][1] = r1;
                b[2 * np + 1][0] = r2; b[2 * np + 1][1] = r3;
            }
#pragma unroll
            for (int mt = 0; mt < 2; mt++)
#pragma unroll
                for (int nt = 0; nt < 8; nt++)
                    imma16832(acc[mt][nt][0], acc[mt][nt][1], acc[mt][nt][2], acc[mt][nt][3],
                              a[mt][0], a[mt][1], a[mt][2], a[mt][3], b[nt][0], b[nt][1]);
        }
        __syncthreads();
        if (k + 3 < NCH) load_chunk(tid, Ap, Bp, DATA, k + 3);
        asm volatile("cp.async.commit_group;" ::: "memory");  // empty groups keep accounting uniform
    }
    asm volatile("cp.async.wait_group 0;" ::: "memory");
    __syncthreads();   // pipeline smem free -> reuse as fp32 tile

    // scatter accum -> smem fp32 tile with dequant scales (1/T folded into sS)
    float* tile = (float*)smem;
    {
        const int r0 = wm * 32 + (lane >> 2);
        const int c0base = wn * 64 + 2 * (lane & 3);
        float sIr[2][2], sSc[8][2];
#pragma unroll
        for (int mt = 0; mt < 2; mt++) {
            sIr[mt][0] = g_qsI[by * 128 + r0 + mt * 16];
            sIr[mt][1] = g_qsI[by * 128 + r0 + mt * 16 + 8];
        }
#pragma unroll
        for (int nt = 0; nt < 8; nt++) {
            sSc[nt][0] = g_qsS[bx * 128 + c0base + nt * 8];
            sSc[nt][1] = g_qsS[bx * 128 + c0base + nt * 8 + 1];
        }
#pragma unroll
        for (int mt = 0; mt < 2; mt++) {
#pragma unroll
            for (int nt = 0; nt < 8; nt++) {
                int r = r0 + mt * 16;
                int c = c0base + nt * 8;
                tile[r * TILE_PAD + c]           = (float)acc[mt][nt][0] * (sIr[mt][0] * sSc[nt][0]);
                tile[r * TILE_PAD + c + 1]       = (float)acc[mt][nt][1] * (sIr[mt][0] * sSc[nt][1]);
                tile[(r + 8) * TILE_PAD + c]     = (float)acc[mt][nt][2] * (sIr[mt][1] * sSc[nt][0]);
                tile[(r + 8) * TILE_PAD + c + 1] = (float)acc[mt][nt][3] * (sIr[mt][1] * sSc[nt][1]);
            }
        }
    }
    __syncthreads();

    const bool dT = (bx == by);
    if (tid < 128) {   // row-side partials (one thread per row)
        int t = tid;
        float m = -3.4e38f, h = -3.4e38f;
#pragma unroll 8
        for (int c = 0; c < 128; c++) {
            float x = tile[t * TILE_PAD + c];
            m = fmaxf(m, x);
            if (!(dT && c == t)) h = fmaxf(h, x);
        }
        float ssum = 0.f;
#pragma unroll 8
        for (int c = 0; c < 128; c++) ssum += __expf(tile[t * TILE_PAD + c] - m);
        int rg = by * 128 + t;
        g_rowMax[bx * BB + rg] = m;
        g_rowSum[bx * BB + rg] = ssum;
        g_rowHn [bx * BB + rg] = h;
        if (dT) g_diag[rg] = tile[t * TILE_PAD + t];
    } else {           // col-side partials (one thread per col)
        int t = tid - 128;
        float m = -3.4e38f, h = -3.4e38f;
#pragma unroll 8
        for (int rr = 0; rr < 128; rr++) {
            float x = tile[rr * TILE_PAD + t];
            m = fmaxf(m, x);
            if (!(dT && rr == t)) h = fmaxf(h, x);
        }
        float ssum = 0.f;
#pragma unroll 8
        for (int rr = 0; rr < 128; rr++) ssum += __expf(tile[rr * TILE_PAD + t] - m);
        int cg = bx * 128 + t;
        g_colMax[by * BB + cg] = m;
        g_colSum[by * BB + cg] = ssum;
        g_colHn [by * BB + cg] = h;
    }
}

// ------------------------- kernel 3: merge partials -> per-row/col loss + block sums ---------
__global__ void combine_kernel() {
    int i = blockIdx.x * blockDim.x + threadIdx.x;  // 0 .. 2*BB-1
    int idx = i & (BB - 1);
    const float *PM, *PS, *PH;
    if (i < BB) { PM = g_rowMax; PS = g_rowSum; PH = g_rowHn; }
    else        { PM = g_colMax; PS = g_colSum; PH = g_colHn; }

    float m = -3.4e38f, h = -3.4e38f;
#pragma unroll 8
    for (int t = 0; t < NT; t++) {
        m = fmaxf(m, PM[t * BB + idx]);
        h = fmaxf(h, PH[t * BB + idx]);
    }
    float s = 0.f;
#pragma unroll 8
    for (int t = 0; t < NT; t++)
        s += PS[t * BB + idx] * __expf(PM[t * BB + idx] - m);

    float d = g_diag[idx];
    float loss;
    if (h > 0.f) {
        // hard negative is the off-diag max; scale it by 1.5
        float M = fmaxf(m, HNW_SCALE * h);
        float S = s * __expf(m - M) - __expf(h - M) + __expf(HNW_SCALE * h - M);
        loss = M + __logf(S) - d;
    } else {
        // masked argmax lands on the zeroed diagonal -> diagonal gets scaled (matches ref)
        float dd = HNW_SCALE * d;
        float snd = s - __expf(d - m);
        float M = fmaxf(h, dd);
        float S = snd * __expf(m - M) + __expf(dd - M);
        loss = M + __logf(S) - dd;
    }

    // block-level deterministic partial sum
    __shared__ float red[256];
    red[threadIdx.x] = loss;
    __syncthreads();
    for (int o = 128; o > 0; o >>= 1) {
        if (threadIdx.x < (unsigned)o) red[threadIdx.x] += red[threadIdx.x + o];
        __syncthreads();
    }
    if (threadIdx.x == 0) g_part[blockIdx.x] = red[0];
}

// ------------------------- kernel 4: tiny deterministic reduction -------------------------
__global__ void finalize_kernel(float* out) {
    __shared__ float red[64];
    if (threadIdx.x < 64) red[threadIdx.x] = g_part[threadIdx.x];
    __syncthreads();
    if (threadIdx.x == 0) {
        float s = 0.f;
#pragma unroll
        for (int i = 0; i < 64; i++) s += red[i];
        out[0] = s / (float)(2 * BB);
    }
}

// ------------------------- launch -------------------------
extern "C" void kernel_launch(void* const* d_in, const int* in_sizes, int n_in,
                              void* d_out, int out_size) {
    const float* I = (const float*)d_in[0];
    const float* S = (const float*)d_in[1];
    float* out = (float*)d_out;

    cudaFuncSetAttribute(gemm_kernel, cudaFuncAttributeMaxDynamicSharedMemorySize, SMEM_BYTES);

    quant_kernel<<<2 * BB, 256>>>(I, S);
    gemm_kernel<<<dim3(NT, NT, 1), 256, SMEM_BYTES>>>();
    combine_kernel<<<(2 * BB) / 256, 256>>>();
    finalize_kernel<<<1, 64>>>(out);
}

// round 6
// speedup vs baseline: 1.6568x; 1.0534x over previous
#include <cuda_runtime.h>
#include <cuda_bf16.h>
#include <cstdint>

// Problem constants
static constexpr int BB  = 8192;   // batch
static constexpr int DK  = 1024;   // embedding dim
static constexpr int NT  = 64;     // 8192 / 128 tiles per side
static constexpr int NCH = 8;      // 1024 / 128 K-chunks (int8: BK=128)
static constexpr float HNW_SCALE = 1.5f;   // 1 + hard_negative_weight

static constexpr int STAGE_BYTES = 32768;            // A(16K) + B(16K) int8
static constexpr int SMEM_BYTES  = 3 * STAGE_BYTES;  // 98304; 2 CTAs/SM

// ------------------------- device scratch (static, no allocs) -------------------------
__device__ __align__(256) int8_t g_Iq[(size_t)BB * DK];
__device__ __align__(256) int8_t g_Sq[(size_t)BB * DK];
__device__ float g_qsI[BB];        // rowmax/127
__device__ float g_qsS[BB];        // rowmax/127 * 20  (1/T folded here)
__device__ float g_rowMax[NT * BB];
__device__ float g_rowSum[NT * BB];
__device__ float g_rowHn [NT * BB];
__device__ float g_colMax[NT * BB];
__device__ float g_colSum[NT * BB];
__device__ float g_colHn [NT * BB];
__device__ float g_diag  [BB];
__device__ float g_part  [64];
__device__ unsigned g_ctr = 0;

// ------------------------- helpers -------------------------
static __device__ __forceinline__ uint32_t smem_u32(const void* p) {
    uint32_t a;
    asm("{ .reg .u64 t; cvta.to.shared.u64 t, %1; cvt.u32.u64 %0, t; }" : "=r"(a) : "l"(p));
    return a;
}
static __device__ __forceinline__ void cp16(uint32_t s, const void* g) {
    asm volatile("cp.async.cg.shared.global [%0], [%1], 16;" :: "r"(s), "l"(g) : "memory");
}
// Swizzled smem addr for a [128 rows][128 B] tile; 16B chunks xor'd by row&7
static __device__ __forceinline__ uint32_t sw_addr(uint32_t base, int row, int kchunk) {
    return base + (uint32_t)(row * 128) + (uint32_t)(((kchunk ^ (row & 7)) << 4));
}
static __device__ __forceinline__ void ldsm_x4(uint32_t& r0, uint32_t& r1, uint32_t& r2,
                                               uint32_t& r3, uint32_t addr) {
    asm volatile("ldmatrix.sync.aligned.m8n8.x4.shared.b16 {%0,%1,%2,%3}, [%4];"
                 : "=r"(r0), "=r"(r1), "=r"(r2), "=r"(r3) : "r"(addr));
}
static __device__ __forceinline__ void imma16832(int& c0, int& c1, int& c2, int& c3,
                                                 uint32_t a0, uint32_t a1, uint32_t a2,
                                                 uint32_t a3, uint32_t b0, uint32_t b1) {
    asm volatile(
        "mma.sync.aligned.m16n8k32.row.col.s32.s8.s8.s32 "
        "{%0,%1,%2,%3}, {%4,%5,%6,%7}, {%8,%9}, {%0,%1,%2,%3};"
        : "+r"(c0), "+r"(c1), "+r"(c2), "+r"(c3)
        : "r"(a0), "r"(a1), "r"(a2), "r"(a3), "r"(b0), "r"(b1));
}

// ------------------------- kernel 1: fp32 -> int8 per-row symmetric quant ----------------
__global__ void __launch_bounds__(256) quant_kernel(const float* __restrict__ I,
                                                    const float* __restrict__ S) {
    const int row = blockIdx.x;
    const bool isI = row < BB;
    const int r = isI ? row : row - BB;
    const float* src = (isI ? I : S) + (size_t)r * DK;
    const int tid = threadIdx.x;

    float4 v = ((const float4*)src)[tid];
    float m = fmaxf(fmaxf(fabsf(v.x), fabsf(v.y)), fmaxf(fabsf(v.z), fabsf(v.w)));
    __shared__ float red[8];
#pragma unroll
    for (int o = 16; o; o >>= 1) m = fmaxf(m, __shfl_xor_sync(~0u, m, o));
    if ((tid & 31) == 0) red[tid >> 5] = m;
    __syncthreads();
    if (tid < 8) {
        float t = red[tid];
#pragma unroll
        for (int o = 4; o; o >>= 1) t = fmaxf(t, __shfl_xor_sync(0xffu, t, o));
        if (tid == 0) red[0] = t;
    }
    __syncthreads();
    m = fmaxf(red[0], 1e-20f);
    const float inv = 127.0f / m;
    char4 q;
    q.x = (char)__float2int_rn(v.x * inv);
    q.y = (char)__float2int_rn(v.y * inv);
    q.z = (char)__float2int_rn(v.z * inv);
    q.w = (char)__float2int_rn(v.w * inv);
    ((char4*)(isI ? g_Iq : g_Sq))[(size_t)r * 256 + tid] = q;
    if (tid == 0) {
        if (isI) g_qsI[r] = m / 127.0f;
        else     g_qsS[r] = (m / 127.0f) * 20.0f;
    }
}

// ------------------------- kernel 2: int8 GEMM tile + register epilogue ------------------
static __device__ __forceinline__ void load_chunk(int tid, const int8_t* Ap,
                                                  const int8_t* Bp,
                                                  uint32_t DATA, int kc) {
    int s = kc % 3;
    uint32_t abase = DATA + (uint32_t)s * STAGE_BYTES;
    uint32_t bbase = abase + 16384u;
    const int8_t* ga0 = Ap + kc * 128;
    const int8_t* gb0 = Bp + kc * 128;
#pragma unroll
    for (int i = 0; i < 4; i++) {
        int v = tid + i * 256;
        int row = v >> 3, cv = v & 7;
        cp16(sw_addr(abase, row, cv), ga0 + (size_t)row * DK + cv * 16);
        cp16(sw_addr(bbase, row, cv), gb0 + (size_t)row * DK + cv * 16);
    }
}

__global__ void __launch_bounds__(256, 2) gemm_kernel() {
    extern __shared__ char smem[];
    const uint32_t DATA = smem_u32(smem);
    const int tid = threadIdx.x, wid = tid >> 5, lane = tid & 31;
    const int wm = wid >> 1, wn = wid & 1;   // 4 x 2 warp grid
    const int bx = blockIdx.x, by = blockIdx.y;

    const int8_t* Ap = g_Iq + (size_t)by * 128 * DK;
    const int8_t* Bp = g_Sq + (size_t)bx * 128 * DK;

    int acc[2][8][4];
#pragma unroll
    for (int mt = 0; mt < 2; mt++)
#pragma unroll
        for (int nt = 0; nt < 8; nt++)
#pragma unroll
            for (int q = 0; q < 4; q++) acc[mt][nt][q] = 0;

    load_chunk(tid, Ap, Bp, DATA, 0);
    asm volatile("cp.async.commit_group;" ::: "memory");
    load_chunk(tid, Ap, Bp, DATA, 1);
    asm volatile("cp.async.commit_group;" ::: "memory");
    load_chunk(tid, Ap, Bp, DATA, 2);
    asm volatile("cp.async.commit_group;" ::: "memory");

    for (int k = 0; k < NCH; k++) {
        asm volatile("cp.async.wait_group 2;" ::: "memory");
        __syncthreads();
        int s = k % 3;
        uint32_t abase = DATA + (uint32_t)s * STAGE_BYTES;
        uint32_t bbase = abase + 16384u;
#pragma unroll
        for (int kk = 0; kk < 4; kk++) {   // 4 x K=32 per 128B chunk-row
            uint32_t a[2][4];
#pragma unroll
            for (int mt = 0; mt < 2; mt++) {
                int row = wm * 32 + mt * 16 + (lane & 15);
                int kch = 2 * kk + (lane >> 4);
                ldsm_x4(a[mt][0], a[mt][1], a[mt][2], a[mt][3], sw_addr(abase, row, kch));
            }
            uint32_t b[8][2];
#pragma unroll
            for (int np = 0; np < 4; np++) {
                int nrow = wn * 64 + np * 16 + (lane & 7) + ((lane >> 4) << 3);
                int kch = 2 * kk + ((lane >> 3) & 1);
                uint32_t r0, r1, r2, r3;
                ldsm_x4(r0, r1, r2, r3, sw_addr(bbase, nrow, kch));
                b[2 * np][0] = r0; b[2 * np][1] = r1;
                b[2 * np + 1][0] = r2; b[2 * np + 1][1] = r3;
            }
#pragma unroll
            for (int mt = 0; mt < 2; mt++)
#pragma unroll
                for (int nt = 0; nt < 8; nt++)
                    imma16832(acc[mt][nt][0], acc[mt][nt][1], acc[mt][nt][2], acc[mt][nt][3],
                              a[mt][0], a[mt][1], a[mt][2], a[mt][3], b[nt][0], b[nt][1]);
        }
        __syncthreads();
        if (k + 3 < NCH) load_chunk(tid, Ap, Bp, DATA, k + 3);
        asm volatile("cp.async.commit_group;" ::: "memory");
    }
    asm volatile("cp.async.wait_group 0;" ::: "memory");
    __syncthreads();   // pipeline smem free -> reuse for tiny epilogue partials

    // ---------------- register epilogue ----------------
    // thread element (mt,nt,q): q = qr*2+qc
    //   r_loc = wm*32 + mt*16 + (lane>>2) + qr*8
    //   c_loc = wn*64 + nt*8 + 2*(lane&3) + qc
    const int rbase = wm * 32 + (lane >> 2);
    const int cbase = wn * 64 + 2 * (lane & 3);
    const bool dT = (bx == by);

    // dequant into x (acc dies here)
    float x[2][8][4];
    {
        float sI[2][2], sS[8][2];
#pragma unroll
        for (int mt = 0; mt < 2; mt++) {
            sI[mt][0] = g_qsI[by * 128 + rbase + mt * 16];
            sI[mt][1] = g_qsI[by * 128 + rbase + mt * 16 + 8];
        }
#pragma unroll
        for (int nt = 0; nt < 8; nt++) {
            sS[nt][0] = g_qsS[bx * 128 + cbase + nt * 8];
            sS[nt][1] = g_qsS[bx * 128 + cbase + nt * 8 + 1];
        }
#pragma unroll
        for (int mt = 0; mt < 2; mt++)
#pragma unroll
            for (int nt = 0; nt < 8; nt++)
#pragma unroll
                for (int qr = 0; qr < 2; qr++)
#pragma unroll
                    for (int qc = 0; qc < 2; qc++)
                        x[mt][nt][qr * 2 + qc] =
                            (float)acc[mt][nt][qr * 2 + qc] * (sI[mt][qr] * sS[nt][qc]);
    }

    float* sm = (float*)smem;
    float* rm = sm;          // [2][128]
    float* rh = sm + 256;    // [2][128]
    float* rs = sm + 512;    // [2][128]
    float* cm = sm + 768;    // [4][128]
    float* ch = sm + 1280;   // [4][128]
    float* cs = sm + 1792;   // [4][128]

    // pass A: maxes (+diag capture)
#pragma unroll
    for (int g = 0; g < 4; g++) {
        int mt = g >> 1, qr = g & 1;
        int r_loc = rbase + mt * 16 + qr * 8;
        float m = -3.4e38f, h = -3.4e38f;
#pragma unroll
        for (int nt = 0; nt < 8; nt++) {
#pragma unroll
            for (int qc = 0; qc < 2; qc++) {
                float v = x[mt][nt][qr * 2 + qc];
                m = fmaxf(m, v);
                int c_loc = cbase + nt * 8 + qc;
                if (dT && c_loc == r_loc) g_diag[by * 128 + r_loc] = v;
                else h = fmaxf(h, v);
            }
        }
        m = fmaxf(m, __shfl_xor_sync(~0u, m, 1));
        m = fmaxf(m, __shfl_xor_sync(~0u, m, 2));
        h = fmaxf(h, __shfl_xor_sync(~0u, h, 1));
        h = fmaxf(h, __shfl_xor_sync(~0u, h, 2));
        if ((lane & 3) == 0) { rm[wn * 128 + r_loc] = m; rh[wn * 128 + r_loc] = h; }
    }
#pragma unroll
    for (int nt = 0; nt < 8; nt++) {
#pragma unroll
        for (int qc = 0; qc < 2; qc++) {
            int c_loc = cbase + nt * 8 + qc;
            float m = -3.4e38f, h = -3.4e38f;
#pragma unroll
            for (int g = 0; g < 4; g++) {
                int mt = g >> 1, qr = g & 1;
                float v = x[mt][nt][qr * 2 + qc];
                m = fmaxf(m, v);
                int r_loc = rbase + mt * 16 + qr * 8;
                if (!(dT && c_loc == r_loc)) h = fmaxf(h, v);
            }
            m = fmaxf(m, __shfl_xor_sync(~0u, m, 4));
            m = fmaxf(m, __shfl_xor_sync(~0u, m, 8));
            m = fmaxf(m, __shfl_xor_sync(~0u, m, 16));
            h = fmaxf(h, __shfl_xor_sync(~0u, h, 4));
            h = fmaxf(h, __shfl_xor_sync(~0u, h, 8));
            h = fmaxf(h, __shfl_xor_sync(~0u, h, 16));
            if ((lane >> 2) == 0) { cm[wm * 128 + c_loc] = m; ch[wm * 128 + c_loc] = h; }
        }
    }
    __syncthreads();

    // pass B: exp sums against the COMBINED maxes (partials then add exactly)
#pragma unroll
    for (int g = 0; g < 4; g++) {
        int mt = g >> 1, qr = g & 1;
        int r_loc = rbase + mt * 16 + qr * 8;
        float mrow = fmaxf(rm[r_loc], rm[128 + r_loc]);
        float s = 0.f;
#pragma unroll
        for (int nt = 0; nt < 8; nt++) {
            s += __expf(x[mt][nt][qr * 2] - mrow);
            s += __expf(x[mt][nt][qr * 2 + 1] - mrow);
        }
        s += __shfl_xor_sync(~0u, s, 1);
        s += __shfl_xor_sync(~0u, s, 2);
        if ((lane & 3) == 0) rs[wn * 128 + r_loc] = s;
    }
#pragma unroll
    for (int nt = 0; nt < 8; nt++) {
#pragma unroll
        for (int qc = 0; qc < 2; qc++) {
            int c_loc = cbase + nt * 8 + qc;
            float mcol = fmaxf(fmaxf(cm[c_loc], cm[128 + c_loc]),
                               fmaxf(cm[256 + c_loc], cm[384 + c_loc]));
            float s = 0.f;
#pragma unroll
            for (int g = 0; g < 4; g++) {
                int mt = g >> 1, qr = g & 1;
                s += __expf(x[mt][nt][qr * 2 + qc] - mcol);
            }
            s += __shfl_xor_sync(~0u, s, 4);
            s += __shfl_xor_sync(~0u, s, 8);
            s += __shfl_xor_sync(~0u, s, 16);
            if ((lane >> 2) == 0) cs[wm * 128 + c_loc] = s;
        }
    }
    __syncthreads();

    // final writes
    if (tid < 128) {
        int r = tid;
        float m = fmaxf(rm[r], rm[128 + r]);
        float h = fmaxf(rh[r], rh[128 + r]);
        float s = rs[r] + rs[128 + r];
        int rg = by * 128 + r;
        g_rowMax[bx * BB + rg] = m;
        g_rowSum[bx * BB + rg] = s;
        g_rowHn [bx * BB + rg] = h;
    } else {
        int c = tid - 128;
        float m = fmaxf(fmaxf(cm[c], cm[128 + c]), fmaxf(cm[256 + c], cm[384 + c]));
        float h = fmaxf(fmaxf(ch[c], ch[128 + c]), fmaxf(ch[256 + c], ch[384 + c]));
        float s = cs[c] + cs[128 + c] + cs[256 + c] + cs[384 + c];
        int cg = bx * 128 + c;
        g_colMax[by * BB + cg] = m;
        g_colSum[by * BB + cg] = s;
        g_colHn [by * BB + cg] = h;
    }
}

// ------------------------- kernel 3: merge partials -> loss; last block finalizes --------
__global__ void combine_kernel(float* __restrict__ out) {
    int i = blockIdx.x * blockDim.x + threadIdx.x;  // 0 .. 2*BB-1
    int idx = i & (BB - 1);
    const float *PM, *PS, *PH;
    if (i < BB) { PM = g_rowMax; PS = g_rowSum; PH = g_rowHn; }
    else        { PM = g_colMax; PS = g_colSum; PH = g_colHn; }

    float m = -3.4e38f, h = -3.4e38f;
#pragma unroll 8
    for (int t = 0; t < NT; t++) {
        m = fmaxf(m, PM[t * BB + idx]);
        h = fmaxf(h, PH[t * BB + idx]);
    }
    float s = 0.f;
#pragma unroll 8
    for (int t = 0; t < NT; t++)
        s += PS[t * BB + idx] * __expf(PM[t * BB + idx] - m);

    float d = g_diag[idx];
    float loss;
    if (h > 0.f) {
        float M = fmaxf(m, HNW_SCALE * h);
        float S = s * __expf(m - M) - __expf(h - M) + __expf(HNW_SCALE * h - M);
        loss = M + __logf(S) - d;
    } else {
        float dd = HNW_SCALE * d;
        float snd = s - __expf(d - m);
        float M = fmaxf(h, dd);
        float S = snd * __expf(m - M) + __expf(dd - M);
        loss = M + __logf(S) - dd;
    }

    __shared__ float red[256];
    __shared__ bool last;
    red[threadIdx.x] = loss;
    __syncthreads();
    for (int o = 128; o > 0; o >>= 1) {
        if (threadIdx.x < (unsigned)o) red[threadIdx.x] += red[threadIdx.x + o];
        __syncthreads();
    }
    if (threadIdx.x == 0) {
        g_part[blockIdx.x] = red[0];
        __threadfence();
        last = (atomicAdd(&g_ctr, 1u) == 63u);
    }
    __syncthreads();
    if (last && threadIdx.x == 0) {
        float t = 0.f;
#pragma unroll
        for (int b = 0; b < 64; b++) t += g_part[b];
        out[0] = t / (float)(2 * BB);
        g_ctr = 0;  // reset for next graph replay
    }
}

// ------------------------- launch -------------------------
extern "C" void kernel_launch(void* const* d_in, const int* in_sizes, int n_in,
                              void* d_out, int out_size) {
    const float* I = (const float*)d_in[0];
    const float* S = (const float*)d_in[1];
    float* out = (float*)d_out;

    cudaFuncSetAttribute(gemm_kernel, cudaFuncAttributeMaxDynamicSharedMemorySize, SMEM_BYTES);

    quant_kernel<<<2 * BB, 256>>>(I, S);
    gemm_kernel<<<dim3(NT, NT, 1), 256, SMEM_BYTES>>>();
    combine_kernel<<<(2 * BB) / 256, 256>>>(out);
}

// round 7
// speedup vs baseline: 1.7370x; 1.0484x over previous
#include <cuda_runtime.h>
#include <cuda_bf16.h>
#include <cstdint>

// Problem constants
static constexpr int BB  = 8192;   // batch
static constexpr int DK  = 1024;   // embedding dim
static constexpr int NT  = 64;     // 8192 / 128 tiles per side
static constexpr int NCH = 8;      // 1024 / 128 K-chunks (int8: BK=128)
static constexpr float HNW_SCALE = 1.5f;   // 1 + hard_negative_weight

static constexpr int STAGE_BYTES = 32768;            // A(16K) + B(16K) int8
static constexpr int SMEM_BYTES  = 3 * STAGE_BYTES;  // 98304; 2 CTAs/SM

// ------------------------- device scratch (static, no allocs) -------------------------
__device__ __align__(256) int8_t g_Iq[(size_t)BB * DK];
__device__ __align__(256) int8_t g_Sq[(size_t)BB * DK];
__device__ float g_qsI[BB];        // rowmax/127
__device__ float g_qsS[BB];        // rowmax/127 * 20  (1/T folded here)
__device__ float g_rowMax[NT * BB];
__device__ float g_rowSum[NT * BB];
__device__ float g_rowHn [NT * BB];
__device__ float g_colMax[NT * BB];
__device__ float g_colSum[NT * BB];
__device__ float g_colHn [NT * BB];
__device__ float g_diag  [BB];
__device__ float g_part  [64];
__device__ unsigned g_ctr = 0;

// ------------------------- helpers -------------------------
static __device__ __forceinline__ uint32_t smem_u32(const void* p) {
    uint32_t a;
    asm("{ .reg .u64 t; cvta.to.shared.u64 t, %1; cvt.u32.u64 %0, t; }" : "=r"(a) : "l"(p));
    return a;
}
static __device__ __forceinline__ void cp16(uint32_t s, const void* g) {
    asm volatile("cp.async.cg.shared.global [%0], [%1], 16;" :: "r"(s), "l"(g) : "memory");
}
// Swizzled smem addr for a [128 rows][128 B] tile; 16B chunks xor'd by row&7
static __device__ __forceinline__ uint32_t sw_addr(uint32_t base, int row, int kchunk) {
    return base + (uint32_t)(row * 128) + (uint32_t)(((kchunk ^ (row & 7)) << 4));
}
static __device__ __forceinline__ void ldsm_x4(uint32_t& r0, uint32_t& r1, uint32_t& r2,
                                               uint32_t& r3, uint32_t addr) {
    asm volatile("ldmatrix.sync.aligned.m8n8.x4.shared.b16 {%0,%1,%2,%3}, [%4];"
                 : "=r"(r0), "=r"(r1), "=r"(r2), "=r"(r3) : "r"(addr));
}
static __device__ __forceinline__ void imma16832(int& c0, int& c1, int& c2, int& c3,
                                                 uint32_t a0, uint32_t a1, uint32_t a2,
                                                 uint32_t a3, uint32_t b0, uint32_t b1) {
    asm volatile(
        "mma.sync.aligned.m16n8k32.row.col.s32.s8.s8.s32 "
        "{%0,%1,%2,%3}, {%4,%5,%6,%7}, {%8,%9}, {%0,%1,%2,%3};"
        : "+r"(c0), "+r"(c1), "+r"(c2), "+r"(c3)
        : "r"(a0), "r"(a1), "r"(a2), "r"(a3), "r"(b0), "r"(b1));
}

// ------------------------- kernel 1: fp32 -> int8 quant (warp-per-row) -------------------
// 32 lanes x 8 float4 = one 1024-elem row per warp; shuffle-only reduction, no barriers.
__global__ void __launch_bounds__(256) quant_kernel(const float* __restrict__ I,
                                                    const float* __restrict__ S) {
    const int w = (blockIdx.x * 256 + threadIdx.x) >> 5;   // global warp id = row 0..16383
    const int lane = threadIdx.x & 31;
    const bool isI = w < BB;
    const int r = isI ? w : w - BB;
    const float4* src = (const float4*)((isI ? I : S) + (size_t)r * DK);

    float4 v[8];
    float m = 0.f;
#pragma unroll
    for (int i = 0; i < 8; i++) {
        v[i] = src[lane + 32 * i];
        m = fmaxf(m, fmaxf(fmaxf(fabsf(v[i].x), fabsf(v[i].y)),
                           fmaxf(fabsf(v[i].z), fabsf(v[i].w))));
    }
#pragma unroll
    for (int o = 16; o; o >>= 1) m = fmaxf(m, __shfl_xor_sync(~0u, m, o));
    m = fmaxf(m, 1e-20f);
    const float inv = 127.0f / m;

    char4* dst = (char4*)((isI ? g_Iq : g_Sq) + (size_t)r * DK);
#pragma unroll
    for (int i = 0; i < 8; i++) {
        char4 q;
        q.x = (char)__float2int_rn(v[i].x * inv);
        q.y = (char)__float2int_rn(v[i].y * inv);
        q.z = (char)__float2int_rn(v[i].z * inv);
        q.w = (char)__float2int_rn(v[i].w * inv);
        dst[lane + 32 * i] = q;
    }
    if (lane == 0) {
        if (isI) g_qsI[r] = m / 127.0f;
        else     g_qsS[r] = (m / 127.0f) * 20.0f;
    }
}

// ------------------------- kernel 2: int8 GEMM tile + register epilogue ------------------
static __device__ __forceinline__ void load_chunk(int tid, const int8_t* Ap,
                                                  const int8_t* Bp,
                                                  uint32_t DATA, int kc) {
    int s = kc % 3;
    uint32_t abase = DATA + (uint32_t)s * STAGE_BYTES;
    uint32_t bbase = abase + 16384u;
    const int8_t* ga0 = Ap + kc * 128;
    const int8_t* gb0 = Bp + kc * 128;
#pragma unroll
    for (int i = 0; i < 4; i++) {
        int v = tid + i * 256;
        int row = v >> 3, cv = v & 7;
        cp16(sw_addr(abase, row, cv), ga0 + (size_t)row * DK + cv * 16);
        cp16(sw_addr(bbase, row, cv), gb0 + (size_t)row * DK + cv * 16);
    }
}

__global__ void __launch_bounds__(256, 2) gemm_kernel() {
    extern __shared__ char smem[];
    const uint32_t DATA = smem_u32(smem);
    const int tid = threadIdx.x, wid = tid >> 5, lane = tid & 31;
    const int wm = wid >> 1, wn = wid & 1;   // 4 x 2 warp grid
    const int bx = blockIdx.x, by = blockIdx.y;

    const int8_t* Ap = g_Iq + (size_t)by * 128 * DK;
    const int8_t* Bp = g_Sq + (size_t)bx * 128 * DK;

    int acc[2][8][4];
#pragma unroll
    for (int mt = 0; mt < 2; mt++)
#pragma unroll
        for (int nt = 0; nt < 8; nt++)
#pragma unroll
            for (int q = 0; q < 4; q++) acc[mt][nt][q] = 0;

    // prologue: 2 stages in flight
    load_chunk(tid, Ap, Bp, DATA, 0);
    asm volatile("cp.async.commit_group;" ::: "memory");
    load_chunk(tid, Ap, Bp, DATA, 1);
    asm volatile("cp.async.commit_group;" ::: "memory");

    // ONE barrier per chunk: prefetch k+2 targets the slot consumed in iter k-1,
    // which every warp finished before arriving at this iteration's barrier.
    for (int k = 0; k < NCH; k++) {
        asm volatile("cp.async.wait_group 1;" ::: "memory");   // stage k arrived
        __syncthreads();
        if (k + 2 < NCH) load_chunk(tid, Ap, Bp, DATA, k + 2);
        asm volatile("cp.async.commit_group;" ::: "memory");   // uniform accounting
        int s = k % 3;
        uint32_t abase = DATA + (uint32_t)s * STAGE_BYTES;
        uint32_t bbase = abase + 16384u;
#pragma unroll
        for (int kk = 0; kk < 4; kk++) {   // 4 x K=32 per 128B chunk-row
            uint32_t a[2][4];
#pragma unroll
            for (int mt = 0; mt < 2; mt++) {
                int row = wm * 32 + mt * 16 + (lane & 15);
                int kch = 2 * kk + (lane >> 4);
                ldsm_x4(a[mt][0], a[mt][1], a[mt][2], a[mt][3], sw_addr(abase, row, kch));
            }
            uint32_t b[8][2];
#pragma unroll
            for (int np = 0; np < 4; np++) {
                int nrow = wn * 64 + np * 16 + (lane & 7) + ((lane >> 4) << 3);
                int kch = 2 * kk + ((lane >> 3) & 1);
                uint32_t r0, r1, r2, r3;
                ldsm_x4(r0, r1, r2, r3, sw_addr(bbase, nrow, kch));
                b[2 * np][0] = r0; b[2 * np][1] = r1;
                b[2 * np + 1][0] = r2; b[2 * np + 1][1] = r3;
            }
#pragma unroll
            for (int mt = 0; mt < 2; mt++)
#pragma unroll
                for (int nt = 0; nt < 8; nt++)
                    imma16832(acc[mt][nt][0], acc[mt][nt][1], acc[mt][nt][2], acc[mt][nt][3],
                              a[mt][0], a[mt][1], a[mt][2], a[mt][3], b[nt][0], b[nt][1]);
        }
    }
    asm volatile("cp.async.wait_group 0;" ::: "memory");
    __syncthreads();   // pipeline smem free -> reuse for tiny epilogue partials

    // ---------------- register epilogue ----------------
    const int rbase = wm * 32 + (lane >> 2);
    const int cbase = wn * 64 + 2 * (lane & 3);
    const bool dT = (bx == by);

    float x[2][8][4];
    {
        float sI[2][2], sS[8][2];
#pragma unroll
        for (int mt = 0; mt < 2; mt++) {
            sI[mt][0] = g_qsI[by * 128 + rbase + mt * 16];
            sI[mt][1] = g_qsI[by * 128 + rbase + mt * 16 + 8];
        }
#pragma unroll
        for (int nt = 0; nt < 8; nt++) {
            sS[nt][0] = g_qsS[bx * 128 + cbase + nt * 8];
            sS[nt][1] = g_qsS[bx * 128 + cbase + nt * 8 + 1];
        }
#pragma unroll
        for (int mt = 0; mt < 2; mt++)
#pragma unroll
            for (int nt = 0; nt < 8; nt++)
#pragma unroll
                for (int qr = 0; qr < 2; qr++)
#pragma unroll
                    for (int qc = 0; qc < 2; qc++)
                        x[mt][nt][qr * 2 + qc] =
                            (float)acc[mt][nt][qr * 2 + qc] * (sI[mt][qr] * sS[nt][qc]);
    }

    float* sm = (float*)smem;
    float* rm = sm;          // [2][128]
    float* rh = sm + 256;    // [2][128]
    float* rs = sm + 512;    // [2][128]
    float* cm = sm + 768;    // [4][128]
    float* ch = sm + 1280;   // [4][128]
    float* cs = sm + 1792;   // [4][128]

    // pass A: maxes (+diag capture)
#pragma unroll
    for (int g = 0; g < 4; g++) {
        int mt = g >> 1, qr = g & 1;
        int r_loc = rbase + mt * 16 + qr * 8;
        float m = -3.4e38f, h = -3.4e38f;
#pragma unroll
        for (int nt = 0; nt < 8; nt++) {
#pragma unroll
            for (int qc = 0; qc < 2; qc++) {
                float v = x[mt][nt][qr * 2 + qc];
                m = fmaxf(m, v);
                int c_loc = cbase + nt * 8 + qc;
                if (dT && c_loc == r_loc) g_diag[by * 128 + r_loc] = v;
                else h = fmaxf(h, v);
            }
        }
        m = fmaxf(m, __shfl_xor_sync(~0u, m, 1));
        m = fmaxf(m, __shfl_xor_sync(~0u, m, 2));
        h = fmaxf(h, __shfl_xor_sync(~0u, h, 1));
        h = fmaxf(h, __shfl_xor_sync(~0u, h, 2));
        if ((lane & 3) == 0) { rm[wn * 128 + r_loc] = m; rh[wn * 128 + r_loc] = h; }
    }
#pragma unroll
    for (int nt = 0; nt < 8; nt++) {
#pragma unroll
        for (int qc = 0; qc < 2; qc++) {
            int c_loc = cbase + nt * 8 + qc;
            float m = -3.4e38f, h = -3.4e38f;
#pragma unroll
            for (int g = 0; g < 4; g++) {
                int mt = g >> 1, qr = g & 1;
                float v = x[mt][nt][qr * 2 + qc];
                m = fmaxf(m, v);
                int r_loc = rbase + mt * 16 + qr * 8;
                if (!(dT && c_loc == r_loc)) h = fmaxf(h, v);
            }
            m = fmaxf(m, __shfl_xor_sync(~0u, m, 4));
            m = fmaxf(m, __shfl_xor_sync(~0u, m, 8));
            m = fmaxf(m, __shfl_xor_sync(~0u, m, 16));
            h = fmaxf(h, __shfl_xor_sync(~0u, h, 4));
            h = fmaxf(h, __shfl_xor_sync(~0u, h, 8));
            h = fmaxf(h, __shfl_xor_sync(~0u, h, 16));
            if ((lane >> 2) == 0) { cm[wm * 128 + c_loc] = m; ch[wm * 128 + c_loc] = h; }
        }
    }
    __syncthreads();

    // pass B: exp sums against the COMBINED maxes (partials then add exactly)
#pragma unroll
    for (int g = 0; g < 4; g++) {
        int mt = g >> 1, qr = g & 1;
        int r_loc = rbase + mt * 16 + qr * 8;
        float mrow = fmaxf(rm[r_loc], rm[128 + r_loc]);
        float s = 0.f;
#pragma unroll
        for (int nt = 0; nt < 8; nt++) {
            s += __expf(x[mt][nt][qr * 2] - mrow);
            s += __expf(x[mt][nt][qr * 2 + 1] - mrow);
        }
        s += __shfl_xor_sync(~0u, s, 1);
        s += __shfl_xor_sync(~0u, s, 2);
        if ((lane & 3) == 0) rs[wn * 128 + r_loc] = s;
    }
#pragma unroll
    for (int nt = 0; nt < 8; nt++) {
#pragma unroll
        for (int qc = 0; qc < 2; qc++) {
            int c_loc = cbase + nt * 8 + qc;
            float mcol = fmaxf(fmaxf(cm[c_loc], cm[128 + c_loc]),
                               fmaxf(cm[256 + c_loc], cm[384 + c_loc]));
            float s = 0.f;
#pragma unroll
            for (int g = 0; g < 4; g++) {
                int mt = g >> 1, qr = g & 1;
                s += __expf(x[mt][nt][qr * 2 + qc] - mcol);
            }
            s += __shfl_xor_sync(~0u, s, 4);
            s += __shfl_xor_sync(~0u, s, 8);
            s += __shfl_xor_sync(~0u, s, 16);
            if ((lane >> 2) == 0) cs[wm * 128 + c_loc] = s;
        }
    }
    __syncthreads();

    // final writes
    if (tid < 128) {
        int r = tid;
        float m = fmaxf(rm[r], rm[128 + r]);
        float h = fmaxf(rh[r], rh[128 + r]);
        float s = rs[r] + rs[128 + r];
        int rg = by * 128 + r;
        g_rowMax[bx * BB + rg] = m;
        g_rowSum[bx * BB + rg] = s;
        g_rowHn [bx * BB + rg] = h;
    } else {
        int c = tid - 128;
        float m = fmaxf(fmaxf(cm[c], cm[128 + c]), fmaxf(cm[256 + c], cm[384 + c]));
        float h = fmaxf(fmaxf(ch[c], ch[128 + c]), fmaxf(ch[256 + c], ch[384 + c]));
        float s = cs[c] + cs[128 + c] + cs[256 + c] + cs[384 + c];
        int cg = bx * 128 + c;
        g_colMax[by * BB + cg] = m;
        g_colSum[by * BB + cg] = s;
        g_colHn [by * BB + cg] = h;
    }
}

// ------------------------- kernel 3: merge partials -> loss; last block finalizes --------
__global__ void combine_kernel(float* __restrict__ out) {
    int i = blockIdx.x * blockDim.x + threadIdx.x;  // 0 .. 2*BB-1
    int idx = i & (BB - 1);
    const float *PM, *PS, *PH;
    if (i < BB) { PM = g_rowMax; PS = g_rowSum; PH = g_rowHn; }
    else        { PM = g_colMax; PS = g_colSum; PH = g_colHn; }

    float m = -3.4e38f, h = -3.4e38f;
#pragma unroll 8
    for (int t = 0; t < NT; t++) {
        m = fmaxf(m, PM[t * BB + idx]);
        h = fmaxf(h, PH[t * BB + idx]);
    }
    float s = 0.f;
#pragma unroll 8
    for (int t = 0; t < NT; t++)
        s += PS[t * BB + idx] * __expf(PM[t * BB + idx] - m);

    float d = g_diag[idx];
    float loss;
    if (h > 0.f) {
        float M = fmaxf(m, HNW_SCALE * h);
        float S = s * __expf(m - M) - __expf(h - M) + __expf(HNW_SCALE * h - M);
        loss = M + __logf(S) - d;
    } else {
        float dd = HNW_SCALE * d;
        float snd = s - __expf(d - m);
        float M = fmaxf(h, dd);
        float S = snd * __expf(m - M) + __expf(dd - M);
        loss = M + __logf(S) - dd;
    }

    __shared__ float red[256];
    __shared__ bool last;
    red[threadIdx.x] = loss;
    __syncthreads();
    for (int o = 128; o > 0; o >>= 1) {
        if (threadIdx.x < (unsigned)o) red[threadIdx.x] += red[threadIdx.x + o];
        __syncthreads();
    }
    if (threadIdx.x == 0) {
        g_part[blockIdx.x] = red[0];
        __threadfence();
        last = (atomicAdd(&g_ctr, 1u) == 63u);
    }
    __syncthreads();
    if (last && threadIdx.x == 0) {
        float t = 0.f;
#pragma unroll
        for (int b = 0; b < 64; b++) t += g_part[b];
        out[0] = t / (float)(2 * BB);
        g_ctr = 0;  // reset for next graph replay
    }
}

// ------------------------- launch -------------------------
extern "C" void kernel_launch(void* const* d_in, const int* in_sizes, int n_in,
                              void* d_out, int out_size) {
    const float* I = (const float*)d_in[0];
    const float* S = (const float*)d_in[1];
    float* out = (float*)d_out;

    cudaFuncSetAttribute(gemm_kernel, cudaFuncAttributeMaxDynamicSharedMemorySize, SMEM_BYTES);

    quant_kernel<<<(2 * BB) / 8, 256>>>(I, S);
    gemm_kernel<<<dim3(NT, NT, 1), 256, SMEM_BYTES>>>();
    combine_kernel<<<(2 * BB) / 256, 256>>>(out);
}

// round 8
// speedup vs baseline: 1.7482x; 1.0064x over previous
#include <cuda_runtime.h>
#include <cuda_bf16.h>
#include <cstdint>

// Problem constants
static constexpr int BB  = 8192;   // batch
static constexpr int DK  = 1024;   // embedding dim
static constexpr int NT  = 64;     // 8192 / 128 tiles per side
static constexpr int NCH = 8;      // 1024 / 128 K-chunks (int8: BK=128)
static constexpr float HNW_SCALE = 1.5f;   // 1 + hard_negative_weight

static constexpr int STAGE_BYTES = 32768;            // A(16K) + B(16K) int8
static constexpr int SMEM_BYTES  = 3 * STAGE_BYTES;  // 98304; 2 CTAs/SM

// ------------------------- device scratch (static, no allocs) -------------------------
__device__ __align__(256) int8_t g_Iq[(size_t)BB * DK];
__device__ __align__(256) int8_t g_Sq[(size_t)BB * DK];
__device__ float g_qsI[BB];        // rowmax/127
__device__ float g_qsS[BB];        // rowmax/127 * 20  (1/T folded here)
__device__ float g_rowMax[NT * BB];
__device__ float g_rowSum[NT * BB];
__device__ float g_rowHn [NT * BB];
__device__ float g_colMax[NT * BB];
__device__ float g_colSum[NT * BB];
__device__ float g_colHn [NT * BB];
__device__ float g_diag  [BB];
__device__ float g_part  [64];
__device__ unsigned g_ctr = 0;

// ------------------------- helpers -------------------------
static __device__ __forceinline__ uint32_t smem_u32(const void* p) {
    uint32_t a;
    asm("{ .reg .u64 t; cvta.to.shared.u64 t, %1; cvt.u32.u64 %0, t; }" : "=r"(a) : "l"(p));
    return a;
}
static __device__ __forceinline__ void cp16(uint32_t s, const void* g) {
    asm volatile("cp.async.cg.shared.global [%0], [%1], 16;" :: "r"(s), "l"(g) : "memory");
}
// Swizzled smem addr for a [128 rows][128 B] tile; 16B chunks xor'd by row&7
static __device__ __forceinline__ uint32_t sw_addr(uint32_t base, int row, int kchunk) {
    return base + (uint32_t)(row * 128) + (uint32_t)(((kchunk ^ (row & 7)) << 4));
}
static __device__ __forceinline__ void ldsm_x4(uint32_t& r0, uint32_t& r1, uint32_t& r2,
                                               uint32_t& r3, uint32_t addr) {
    asm volatile("ldmatrix.sync.aligned.m8n8.x4.shared.b16 {%0,%1,%2,%3}, [%4];"
                 : "=r"(r0), "=r"(r1), "=r"(r2), "=r"(r3) : "r"(addr));
}
static __device__ __forceinline__ void imma16832(int& c0, int& c1, int& c2, int& c3,
                                                 uint32_t a0, uint32_t a1, uint32_t a2,
                                                 uint32_t a3, uint32_t b0, uint32_t b1) {
    asm volatile(
        "mma.sync.aligned.m16n8k32.row.col.s32.s8.s8.s32 "
        "{%0,%1,%2,%3}, {%4,%5,%6,%7}, {%8,%9}, {%0,%1,%2,%3};"
        : "+r"(c0), "+r"(c1), "+r"(c2), "+r"(c3)
        : "r"(a0), "r"(a1), "r"(a2), "r"(a3), "r"(b0), "r"(b1));
}

// ------------------------- kernel 1: fp32 -> int8 quant (cp.async staged) ----------------
// Warp-per-row; row parked in smem via cp.async (each lane touches ONLY its own 128 B,
// so wait_group 0 alone guarantees visibility — no barriers). Two LDS.128 sweeps.
__global__ void __launch_bounds__(256) quant_kernel(const float* __restrict__ I,
                                                    const float* __restrict__ S) {
    __shared__ __align__(16) char stage[8][4096];
    const int wib = threadIdx.x >> 5;                       // warp in block 0..7
    const int w = blockIdx.x * 8 + wib;                     // global row 0..16383
    const int lane = threadIdx.x & 31;
    const bool isI = w < BB;
    const int r = isI ? w : w - BB;
    const float* src = (isI ? I : S) + (size_t)r * DK;
    const uint32_t sb = smem_u32(&stage[wib][0]) + (uint32_t)lane * 16u;

#pragma unroll
    for (int i = 0; i < 8; i++)
        cp16(sb + i * 512u, src + (size_t)lane * 4 + i * 128);
    asm volatile("cp.async.commit_group;" ::: "memory");
    asm volatile("cp.async.wait_group 0;" ::: "memory");

    const float4* mine = (const float4*)(&stage[wib][lane * 16]);
    float m = 0.f;
#pragma unroll
    for (int i = 0; i < 8; i++) {
        float4 v = mine[i * 32];                            // +512 B per step
        m = fmaxf(m, fmaxf(fmaxf(fabsf(v.x), fabsf(v.y)),
                           fmaxf(fabsf(v.z), fabsf(v.w))));
    }
#pragma unroll
    for (int o = 16; o; o >>= 1) m = fmaxf(m, __shfl_xor_sync(~0u, m, o));
    m = fmaxf(m, 1e-20f);
    const float inv = 127.0f / m;

    char4* dst = (char4*)((isI ? g_Iq : g_Sq) + (size_t)r * DK);
#pragma unroll
    for (int i = 0; i < 8; i++) {
        float4 v = mine[i * 32];
        char4 q;
        q.x = (char)__float2int_rn(v.x * inv);
        q.y = (char)__float2int_rn(v.y * inv);
        q.z = (char)__float2int_rn(v.z * inv);
        q.w = (char)__float2int_rn(v.w * inv);
        dst[lane + 32 * i] = q;
    }
    if (lane == 0) {
        if (isI) g_qsI[r] = m / 127.0f;
        else     g_qsS[r] = (m / 127.0f) * 20.0f;
    }
}

// ------------------------- kernel 2: int8 GEMM tile + register epilogue ------------------
static __device__ __forceinline__ void load_chunk(int tid, const int8_t* Ap,
                                                  const int8_t* Bp,
                                                  uint32_t DATA, int kc) {
    int s = kc % 3;
    uint32_t abase = DATA + (uint32_t)s * STAGE_BYTES;
    uint32_t bbase = abase + 16384u;
    const int8_t* ga0 = Ap + kc * 128;
    const int8_t* gb0 = Bp + kc * 128;
#pragma unroll
    for (int i = 0; i < 4; i++) {
        int v = tid + i * 256;
        int row = v >> 3, cv = v & 7;
        cp16(sw_addr(abase, row, cv), ga0 + (size_t)row * DK + cv * 16);
        cp16(sw_addr(bbase, row, cv), gb0 + (size_t)row * DK + cv * 16);
    }
}

__global__ void __launch_bounds__(256, 2) gemm_kernel() {
    extern __shared__ char smem[];
    const uint32_t DATA = smem_u32(smem);
    const int tid = threadIdx.x, wid = tid >> 5, lane = tid & 31;
    const int wm = wid >> 1, wn = wid & 1;   // 4 x 2 warp grid
    const int bx = blockIdx.x, by = blockIdx.y;

    const int8_t* Ap = g_Iq + (size_t)by * 128 * DK;
    const int8_t* Bp = g_Sq + (size_t)bx * 128 * DK;

    int acc[2][8][4];
#pragma unroll
    for (int mt = 0; mt < 2; mt++)
#pragma unroll
        for (int nt = 0; nt < 8; nt++)
#pragma unroll
            for (int q = 0; q < 4; q++) acc[mt][nt][q] = 0;

    load_chunk(tid, Ap, Bp, DATA, 0);
    asm volatile("cp.async.commit_group;" ::: "memory");
    load_chunk(tid, Ap, Bp, DATA, 1);
    asm volatile("cp.async.commit_group;" ::: "memory");

    // ONE barrier per chunk: prefetch k+2 targets the slot consumed in iter k-1.
    for (int k = 0; k < NCH; k++) {
        asm volatile("cp.async.wait_group 1;" ::: "memory");   // stage k arrived
        __syncthreads();
        if (k + 2 < NCH) load_chunk(tid, Ap, Bp, DATA, k + 2);
        asm volatile("cp.async.commit_group;" ::: "memory");   // uniform accounting
        int s = k % 3;
        uint32_t abase = DATA + (uint32_t)s * STAGE_BYTES;
        uint32_t bbase = abase + 16384u;
#pragma unroll
        for (int kk = 0; kk < 4; kk++) {   // 4 x K=32 per 128B chunk-row
            uint32_t a[2][4];
#pragma unroll
            for (int mt = 0; mt < 2; mt++) {
                int row = wm * 32 + mt * 16 + (lane & 15);
                int kch = 2 * kk + (lane >> 4);
                ldsm_x4(a[mt][0], a[mt][1], a[mt][2], a[mt][3], sw_addr(abase, row, kch));
            }
            uint32_t b[8][2];
#pragma unroll
            for (int np = 0; np < 4; np++) {
                int nrow = wn * 64 + np * 16 + (lane & 7) + ((lane >> 4) << 3);
                int kch = 2 * kk + ((lane >> 3) & 1);
                uint32_t r0, r1, r2, r3;
                ldsm_x4(r0, r1, r2, r3, sw_addr(bbase, nrow, kch));
                b[2 * np][0] = r0; b[2 * np][1] = r1;
                b[2 * np + 1][0] = r2; b[2 * np + 1][1] = r3;
            }
#pragma unroll
            for (int mt = 0; mt < 2; mt++)
#pragma unroll
                for (int nt = 0; nt < 8; nt++)
                    imma16832(acc[mt][nt][0], acc[mt][nt][1], acc[mt][nt][2], acc[mt][nt][3],
                              a[mt][0], a[mt][1], a[mt][2], a[mt][3], b[nt][0], b[nt][1]);
        }
    }
    asm volatile("cp.async.wait_group 0;" ::: "memory");
    __syncthreads();   // pipeline smem free -> reuse for tiny epilogue partials

    // ---------------- register epilogue ----------------
    const int rbase = wm * 32 + (lane >> 2);
    const int cbase = wn * 64 + 2 * (lane & 3);
    const bool dT = (bx == by);

    float x[2][8][4];
    {
        float sI[2][2], sS[8][2];
#pragma unroll
        for (int mt = 0; mt < 2; mt++) {
            sI[mt][0] = g_qsI[by * 128 + rbase + mt * 16];
            sI[mt][1] = g_qsI[by * 128 + rbase + mt * 16 + 8];
        }
#pragma unroll
        for (int nt = 0; nt < 8; nt++) {
            sS[nt][0] = g_qsS[bx * 128 + cbase + nt * 8];
            sS[nt][1] = g_qsS[bx * 128 + cbase + nt * 8 + 1];
        }
#pragma unroll
        for (int mt = 0; mt < 2; mt++)
#pragma unroll
            for (int nt = 0; nt < 8; nt++)
#pragma unroll
                for (int qr = 0; qr < 2; qr++)
#pragma unroll
                    for (int qc = 0; qc < 2; qc++)
                        x[mt][nt][qr * 2 + qc] =
                            (float)acc[mt][nt][qr * 2 + qc] * (sI[mt][qr] * sS[nt][qc]);
    }

    float* sm = (float*)smem;
    float* rm = sm;          // [2][128]
    float* rh = sm + 256;    // [2][128]
    float* rs = sm + 512;    // [2][128]
    float* cm = sm + 768;    // [4][128]
    float* ch = sm + 1280;   // [4][128]
    float* cs = sm + 1792;   // [4][128]

    // pass A: maxes (+diag capture)
#pragma unroll
    for (int g = 0; g < 4; g++) {
        int mt = g >> 1, qr = g & 1;
        int r_loc = rbase + mt * 16 + qr * 8;
        float m = -3.4e38f, h = -3.4e38f;
#pragma unroll
        for (int nt = 0; nt < 8; nt++) {
#pragma unroll
            for (int qc = 0; qc < 2; qc++) {
                float v = x[mt][nt][qr * 2 + qc];
                m = fmaxf(m, v);
                int c_loc = cbase + nt * 8 + qc;
                if (dT && c_loc == r_loc) g_diag[by * 128 + r_loc] = v;
                else h = fmaxf(h, v);
            }
        }
        m = fmaxf(m, __shfl_xor_sync(~0u, m, 1));
        m = fmaxf(m, __shfl_xor_sync(~0u, m, 2));
        h = fmaxf(h, __shfl_xor_sync(~0u, h, 1));
        h = fmaxf(h, __shfl_xor_sync(~0u, h, 2));
        if ((lane & 3) == 0) { rm[wn * 128 + r_loc] = m; rh[wn * 128 + r_loc] = h; }
    }
#pragma unroll
    for (int nt = 0; nt < 8; nt++) {
#pragma unroll
        for (int qc = 0; qc < 2; qc++) {
            int c_loc = cbase + nt * 8 + qc;
            float m = -3.4e38f, h = -3.4e38f;
#pragma unroll
            for (int g = 0; g < 4; g++) {
                int mt = g >> 1, qr = g & 1;
                float v = x[mt][nt][qr * 2 + qc];
                m = fmaxf(m, v);
                int r_loc = rbase + mt * 16 + qr * 8;
                if (!(dT && c_loc == r_loc)) h = fmaxf(h, v);
            }
            m = fmaxf(m, __shfl_xor_sync(~0u, m, 4));
            m = fmaxf(m, __shfl_xor_sync(~0u, m, 8));
            m = fmaxf(m, __shfl_xor_sync(~0u, m, 16));
            h = fmaxf(h, __shfl_xor_sync(~0u, h, 4));
            h = fmaxf(h, __shfl_xor_sync(~0u, h, 8));
            h = fmaxf(h, __shfl_xor_sync(~0u, h, 16));
            if ((lane >> 2) == 0) { cm[wm * 128 + c_loc] = m; ch[wm * 128 + c_loc] = h; }
        }
    }
    __syncthreads();

    // pass B: exp sums against the COMBINED maxes (partials then add exactly)
#pragma unroll
    for (int g = 0; g < 4; g++) {
        int mt = g >> 1, qr = g & 1;
        int r_loc = rbase + mt * 16 + qr * 8;
        float mrow = fmaxf(rm[r_loc], rm[128 + r_loc]);
        float s = 0.f;
#pragma unroll
        for (int nt = 0; nt < 8; nt++) {
            s += __expf(x[mt][nt][qr * 2] - mrow);
            s += __expf(x[mt][nt][qr * 2 + 1] - mrow);
        }
        s += __shfl_xor_sync(~0u, s, 1);
        s += __shfl_xor_sync(~0u, s, 2);
        if ((lane & 3) == 0) rs[wn * 128 + r_loc] = s;
    }
#pragma unroll
    for (int nt = 0; nt < 8; nt++) {
#pragma unroll
        for (int qc = 0; qc < 2; qc++) {
            int c_loc = cbase + nt * 8 + qc;
            float mcol = fmaxf(fmaxf(cm[c_loc], cm[128 + c_loc]),
                               fmaxf(cm[256 + c_loc], cm[384 + c_loc]));
            float s = 0.f;
#pragma unroll
            for (int g = 0; g < 4; g++) {
                int mt = g >> 1, qr = g & 1;
                s += __expf(x[mt][nt][qr * 2 + qc] - mcol);
            }
            s += __shfl_xor_sync(~0u, s, 4);
            s += __shfl_xor_sync(~0u, s, 8);
            s += __shfl_xor_sync(~0u, s, 16);
            if ((lane >> 2) == 0) cs[wm * 128 + c_loc] = s;
        }
    }
    __syncthreads();

    // final writes
    if (tid < 128) {
        int r = tid;
        float m = fmaxf(rm[r], rm[128 + r]);
        float h = fmaxf(rh[r], rh[128 + r]);
        float s = rs[r] + rs[128 + r];
        int rg = by * 128 + r;
        g_rowMax[bx * BB + rg] = m;
        g_rowSum[bx * BB + rg] = s;
        g_rowHn [bx * BB + rg] = h;
    } else {
        int c = tid - 128;
        float m = fmaxf(fmaxf(cm[c], cm[128 + c]), fmaxf(cm[256 + c], cm[384 + c]));
        float h = fmaxf(fmaxf(ch[c], ch[128 + c]), fmaxf(ch[256 + c], ch[384 + c]));
        float s = cs[c] + cs[128 + c] + cs[256 + c] + cs[384 + c];
        int cg = bx * 128 + c;
        g_colMax[by * BB + cg] = m;
        g_colSum[by * BB + cg] = s;
        g_colHn [by * BB + cg] = h;
    }
}

// ------------------------- kernel 3: merge partials -> loss; last block finalizes --------
__global__ void combine_kernel(float* __restrict__ out) {
    int i = blockIdx.x * blockDim.x + threadIdx.x;  // 0 .. 2*BB-1
    int idx = i & (BB - 1);
    const float *PM, *PS, *PH;
    if (i < BB) { PM = g_rowMax; PS = g_rowSum; PH = g_rowHn; }
    else        { PM = g_colMax; PS = g_colSum; PH = g_colHn; }

    float m = -3.4e38f, h = -3.4e38f;
#pragma unroll 8
    for (int t = 0; t < NT; t++) {
        m = fmaxf(m, PM[t * BB + idx]);
        h = fmaxf(h, PH[t * BB + idx]);
    }
    float s = 0.f;
#pragma unroll 8
    for (int t = 0; t < NT; t++)
        s += PS[t * BB + idx] * __expf(PM[t * BB + idx] - m);

    float d = g_diag[idx];
    float loss;
    if (h > 0.f) {
        float M = fmaxf(m, HNW_SCALE * h);
        float S = s * __expf(m - M) - __expf(h - M) + __expf(HNW_SCALE * h - M);
        loss = M + __logf(S) - d;
    } else {
        float dd = HNW_SCALE * d;
        float snd = s - __expf(d - m);
        float M = fmaxf(h, dd);
        float S = snd * __expf(m - M) + __expf(dd - M);
        loss = M + __logf(S) - dd;
    }

    __shared__ float red[256];
    __shared__ bool last;
    red[threadIdx.x] = loss;
    __syncthreads();
    for (int o = 128; o > 0; o >>= 1) {
        if (threadIdx.x < (unsigned)o) red[threadIdx.x] += red[threadIdx.x + o];
        __syncthreads();
    }
    if (threadIdx.x == 0) {
        g_part[blockIdx.x] = red[0];
        __threadfence();
        last = (atomicAdd(&g_ctr, 1u) == 63u);
    }
    __syncthreads();
    if (last && threadIdx.x == 0) {
        float t = 0.f;
#pragma unroll
        for (int b = 0; b < 64; b++) t += g_part[b];
        out[0] = t / (float)(2 * BB);
        g_ctr = 0;  // reset for next graph replay
    }
}

// ------------------------- launch -------------------------
extern "C" void kernel_launch(void* const* d_in, const int* in_sizes, int n_in,
                              void* d_out, int out_size) {
    const float* I = (const float*)d_in[0];
    const float* S = (const float*)d_in[1];
    float* out = (float*)d_out;

    cudaFuncSetAttribute(gemm_kernel, cudaFuncAttributeMaxDynamicSharedMemorySize, SMEM_BYTES);

    quant_kernel<<<(2 * BB) / 8, 256>>>(I, S);
    gemm_kernel<<<dim3(NT, NT, 1), 256, SMEM_BYTES>>>();
    combine_kernel<<<(2 * BB) / 256, 256>>>(out);
}

// round 9
// speedup vs baseline: 1.7628x; 1.0084x over previous
#include <cuda_runtime.h>
#include <cuda_bf16.h>
#include <cstdint>

// Problem constants
static constexpr int BB  = 8192;   // batch
static constexpr int DK  = 1024;   // embedding dim
static constexpr int NT  = 64;     // 8192 / 128 tiles per side
static constexpr int NCH = 8;      // 1024 / 128 K-chunks (int8: BK=128)
static constexpr float HNW_SCALE = 1.5f;   // 1 + hard_negative_weight

static constexpr int STAGE_BYTES = 32768;            // A(16K) + B(16K) int8
static constexpr int SMEM_BYTES  = 3 * STAGE_BYTES;  // 98304; 2 CTAs/SM

static constexpr int QBLK = 592;   // quant: 4 CTAs/SM persistent-ish
static constexpr int QWARPS = QBLK * 8;

// ------------------------- device scratch (static, no allocs) -------------------------
__device__ __align__(256) int8_t g_Iq[(size_t)BB * DK];
__device__ __align__(256) int8_t g_Sq[(size_t)BB * DK];
__device__ float g_qsI[BB];        // rowmax/127
__device__ float g_qsS[BB];        // rowmax/127 * 20  (1/T folded here)
__device__ float g_rowMax[NT * BB];
__device__ float g_rowSum[NT * BB];
__device__ float g_rowHn [NT * BB];
__device__ float g_colMax[NT * BB];
__device__ float g_colSum[NT * BB];
__device__ float g_colHn [NT * BB];
__device__ float g_diag  [BB];
__device__ float g_part  [64];
__device__ unsigned g_ctr = 0;

// ------------------------- helpers -------------------------
static __device__ __forceinline__ uint32_t smem_u32(const void* p) {
    uint32_t a;
    asm("{ .reg .u64 t; cvta.to.shared.u64 t, %1; cvt.u32.u64 %0, t; }" : "=r"(a) : "l"(p));
    return a;
}
static __device__ __forceinline__ void cp16(uint32_t s, const void* g) {
    asm volatile("cp.async.cg.shared.global [%0], [%1], 16;" :: "r"(s), "l"(g) : "memory");
}
// Swizzled smem addr for a [128 rows][128 B] tile; 16B chunks xor'd by row&7
static __device__ __forceinline__ uint32_t sw_addr(uint32_t base, int row, int kchunk) {
    return base + (uint32_t)(row * 128) + (uint32_t)(((kchunk ^ (row & 7)) << 4));
}
static __device__ __forceinline__ void ldsm_x4(uint32_t& r0, uint32_t& r1, uint32_t& r2,
                                               uint32_t& r3, uint32_t addr) {
    asm volatile("ldmatrix.sync.aligned.m8n8.x4.shared.b16 {%0,%1,%2,%3}, [%4];"
                 : "=r"(r0), "=r"(r1), "=r"(r2), "=r"(r3) : "r"(addr));
}
static __device__ __forceinline__ void imma16832(int& c0, int& c1, int& c2, int& c3,
                                                 uint32_t a0, uint32_t a1, uint32_t a2,
                                                 uint32_t a3, uint32_t b0, uint32_t b1) {
    asm volatile(
        "mma.sync.aligned.m16n8k32.row.col.s32.s8.s8.s32 "
        "{%0,%1,%2,%3}, {%4,%5,%6,%7}, {%8,%9}, {%0,%1,%2,%3};"
        : "+r"(c0), "+r"(c1), "+r"(c2), "+r"(c3)
        : "r"(a0), "r"(a1), "r"(a2), "r"(a3), "r"(b0), "r"(b1));
}

// ------------------------- kernel 1: fp32 -> int8 quant (persistent warps) ---------------
// 4736 warps grid-stride over 16384 rows (3-4 rows/warp). Register-resident row,
// shuffle-only reduction, no smem, no block barriers.
__global__ void __launch_bounds__(256) quant_kernel(const float* __restrict__ I,
                                                    const float* __restrict__ S) {
    const int gwarp = (blockIdx.x * 256 + threadIdx.x) >> 5;
    const int lane = threadIdx.x & 31;

    for (int w = gwarp; w < 2 * BB; w += QWARPS) {
        const bool isI = w < BB;
        const int r = isI ? w : w - BB;
        const float4* src = (const float4*)((isI ? I : S) + (size_t)r * DK);

        float4 v[8];
        float m = 0.f;
#pragma unroll
        for (int i = 0; i < 8; i++) {
            v[i] = src[lane + 32 * i];
            m = fmaxf(m, fmaxf(fmaxf(fabsf(v[i].x), fabsf(v[i].y)),
                               fmaxf(fabsf(v[i].z), fabsf(v[i].w))));
        }
#pragma unroll
        for (int o = 16; o; o >>= 1) m = fmaxf(m, __shfl_xor_sync(~0u, m, o));
        m = fmaxf(m, 1e-20f);
        const float inv = 127.0f / m;

        char4* dst = (char4*)((isI ? g_Iq : g_Sq) + (size_t)r * DK);
#pragma unroll
        for (int i = 0; i < 8; i++) {
            char4 q;
            q.x = (char)__float2int_rn(v[i].x * inv);
            q.y = (char)__float2int_rn(v[i].y * inv);
            q.z = (char)__float2int_rn(v[i].z * inv);
            q.w = (char)__float2int_rn(v[i].w * inv);
            dst[lane + 32 * i] = q;
        }
        if (lane == 0) {
            if (isI) g_qsI[r] = m / 127.0f;
            else     g_qsS[r] = (m / 127.0f) * 20.0f;
        }
    }
}

// ------------------------- kernel 2: int8 GEMM tile + register epilogue ------------------
static __device__ __forceinline__ void load_chunk(int tid, const int8_t* Ap,
                                                  const int8_t* Bp,
                                                  uint32_t DATA, int kc) {
    int s = kc % 3;
    uint32_t abase = DATA + (uint32_t)s * STAGE_BYTES;
    uint32_t bbase = abase + 16384u;
    const int8_t* ga0 = Ap + kc * 128;
    const int8_t* gb0 = Bp + kc * 128;
#pragma unroll
    for (int i = 0; i < 4; i++) {
        int v = tid + i * 256;
        int row = v >> 3, cv = v & 7;
        cp16(sw_addr(abase, row, cv), ga0 + (size_t)row * DK + cv * 16);
        cp16(sw_addr(bbase, row, cv), gb0 + (size_t)row * DK + cv * 16);
    }
}

__global__ void __launch_bounds__(256, 2) gemm_kernel() {
    extern __shared__ char smem[];
    const uint32_t DATA = smem_u32(smem);
    const int tid = threadIdx.x, wid = tid >> 5, lane = tid & 31;
    const int wm = wid >> 1, wn = wid & 1;   // 4 x 2 warp grid
    const int bx = blockIdx.x, by = blockIdx.y;

    const int8_t* Ap = g_Iq + (size_t)by * 128 * DK;
    const int8_t* Bp = g_Sq + (size_t)bx * 128 * DK;

    int acc[2][8][4];
#pragma unroll
    for (int mt = 0; mt < 2; mt++)
#pragma unroll
        for (int nt = 0; nt < 8; nt++)
#pragma unroll
            for (int q = 0; q < 4; q++) acc[mt][nt][q] = 0;

    load_chunk(tid, Ap, Bp, DATA, 0);
    asm volatile("cp.async.commit_group;" ::: "memory");
    load_chunk(tid, Ap, Bp, DATA, 1);
    asm volatile("cp.async.commit_group;" ::: "memory");

    // ONE barrier per chunk: prefetch k+2 targets the slot consumed in iter k-1.
    for (int k = 0; k < NCH; k++) {
        asm volatile("cp.async.wait_group 1;" ::: "memory");   // stage k arrived
        __syncthreads();
        if (k + 2 < NCH) load_chunk(tid, Ap, Bp, DATA, k + 2);
        asm volatile("cp.async.commit_group;" ::: "memory");   // uniform accounting
        int s = k % 3;
        uint32_t abase = DATA + (uint32_t)s * STAGE_BYTES;
        uint32_t bbase = abase + 16384u;
#pragma unroll
        for (int kk = 0; kk < 4; kk++) {   // 4 x K=32 per 128B chunk-row
            uint32_t a[2][4];
#pragma unroll
            for (int mt = 0; mt < 2; mt++) {
                int row = wm * 32 + mt * 16 + (lane & 15);
                int kch = 2 * kk + (lane >> 4);
                ldsm_x4(a[mt][0], a[mt][1], a[mt][2], a[mt][3], sw_addr(abase, row, kch));
            }
            uint32_t b[8][2];
#pragma unroll
            for (int np = 0; np < 4; np++) {
                int nrow = wn * 64 + np * 16 + (lane & 7) + ((lane >> 4) << 3);
                int kch = 2 * kk + ((lane >> 3) & 1);
                uint32_t r0, r1, r2, r3;
                ldsm_x4(r0, r1, r2, r3, sw_addr(bbase, nrow, kch));
                b[2 * np][0] = r0; b[2 * np][1] = r1;
                b[2 * np + 1][0] = r2; b[2 * np + 1][1] = r3;
            }
#pragma unroll
            for (int mt = 0; mt < 2; mt++)
#pragma unroll
                for (int nt = 0; nt < 8; nt++)
                    imma16832(acc[mt][nt][0], acc[mt][nt][1], acc[mt][nt][2], acc[mt][nt][3],
                              a[mt][0], a[mt][1], a[mt][2], a[mt][3], b[nt][0], b[nt][1]);
        }
    }
    asm volatile("cp.async.wait_group 0;" ::: "memory");
    __syncthreads();   // pipeline smem free -> reuse for tiny epilogue partials

    // ---------------- register epilogue ----------------
    const int rbase = wm * 32 + (lane >> 2);
    const int cbase = wn * 64 + 2 * (lane & 3);
    const bool dT = (bx == by);

    float x[2][8][4];
    {
        float sI[2][2], sS[8][2];
#pragma unroll
        for (int mt = 0; mt < 2; mt++) {
            sI[mt][0] = g_qsI[by * 128 + rbase + mt * 16];
            sI[mt][1] = g_qsI[by * 128 + rbase + mt * 16 + 8];
        }
#pragma unroll
        for (int nt = 0; nt < 8; nt++) {
            sS[nt][0] = g_qsS[bx * 128 + cbase + nt * 8];
            sS[nt][1] = g_qsS[bx * 128 + cbase + nt * 8 + 1];
        }
#pragma unroll
        for (int mt = 0; mt < 2; mt++)
#pragma unroll
            for (int nt = 0; nt < 8; nt++)
#pragma unroll
                for (int qr = 0; qr < 2; qr++)
#pragma unroll
                    for (int qc = 0; qc < 2; qc++)
                        x[mt][nt][qr * 2 + qc] =
                            (float)acc[mt][nt][qr * 2 + qc] * (sI[mt][qr] * sS[nt][qc]);
    }

    float* sm = (float*)smem;
    float* rm = sm;          // [2][128]
    float* rh = sm + 256;    // [2][128]
    float* rs = sm + 512;    // [2][128]
    float* cm = sm + 768;    // [4][128]
    float* ch = sm + 1280;   // [4][128]
    float* cs = sm + 1792;   // [4][128]

    // pass A: maxes (+diag capture)
#pragma unroll
    for (int g = 0; g < 4; g++) {
        int mt = g >> 1, qr = g & 1;
        int r_loc = rbase + mt * 16 + qr * 8;
        float m = -3.4e38f, h = -3.4e38f;
#pragma unroll
        for (int nt = 0; nt < 8; nt++) {
#pragma unroll
            for (int qc = 0; qc < 2; qc++) {
                float v = x[mt][nt][qr * 2 + qc];
                m = fmaxf(m, v);
                int c_loc = cbase + nt * 8 + qc;
                if (dT && c_loc == r_loc) g_diag[by * 128 + r_loc] = v;
                else h = fmaxf(h, v);
            }
        }
        m = fmaxf(m, __shfl_xor_sync(~0u, m, 1));
        m = fmaxf(m, __shfl_xor_sync(~0u, m, 2));
        h = fmaxf(h, __shfl_xor_sync(~0u, h, 1));
        h = fmaxf(h, __shfl_xor_sync(~0u, h, 2));
        if ((lane & 3) == 0) { rm[wn * 128 + r_loc] = m; rh[wn * 128 + r_loc] = h; }
    }
#pragma unroll
    for (int nt = 0; nt < 8; nt++) {
#pragma unroll
        for (int qc = 0; qc < 2; qc++) {
            int c_loc = cbase + nt * 8 + qc;
            float m = -3.4e38f, h = -3.4e38f;
#pragma unroll
            for (int g = 0; g < 4; g++) {
                int mt = g >> 1, qr = g & 1;
                float v = x[mt][nt][qr * 2 + qc];
                m = fmaxf(m, v);
                int r_loc = rbase + mt * 16 + qr * 8;
                if (!(dT && c_loc == r_loc)) h = fmaxf(h, v);
            }
            m = fmaxf(m, __shfl_xor_sync(~0u, m, 4));
            m = fmaxf(m, __shfl_xor_sync(~0u, m, 8));
            m = fmaxf(m, __shfl_xor_sync(~0u, m, 16));
            h = fmaxf(h, __shfl_xor_sync(~0u, h, 4));
            h = fmaxf(h, __shfl_xor_sync(~0u, h, 8));
            h = fmaxf(h, __shfl_xor_sync(~0u, h, 16));
            if ((lane >> 2) == 0) { cm[wm * 128 + c_loc] = m; ch[wm * 128 + c_loc] = h; }
        }
    }
    __syncthreads();

    // pass B: exp sums against the COMBINED maxes (partials then add exactly)
#pragma unroll
    for (int g = 0; g < 4; g++) {
        int mt = g >> 1, qr = g & 1;
        int r_loc = rbase + mt * 16 + qr * 8;
        float mrow = fmaxf(rm[r_loc], rm[128 + r_loc]);
        float s = 0.f;
#pragma unroll
        for (int nt = 0; nt < 8; nt++) {
            s += __expf(x[mt][nt][qr * 2] - mrow);
            s += __expf(x[mt][nt][qr * 2 + 1] - mrow);
        }
        s += __shfl_xor_sync(~0u, s, 1);
        s += __shfl_xor_sync(~0u, s, 2);
        if ((lane & 3) == 0) rs[wn * 128 + r_loc] = s;
    }
#pragma unroll
    for (int nt = 0; nt < 8; nt++) {
#pragma unroll
        for (int qc = 0; qc < 2; qc++) {
            int c_loc = cbase + nt * 8 + qc;
            float mcol = fmaxf(fmaxf(cm[c_loc], cm[128 + c_loc]),
                               fmaxf(cm[256 + c_loc], cm[384 + c_loc]));
            float s = 0.f;
#pragma unroll
            for (int g = 0; g < 4; g++) {
                int mt = g >> 1, qr = g & 1;
                s += __expf(x[mt][nt][qr * 2 + qc] - mcol);
            }
            s += __shfl_xor_sync(~0u, s, 4);
            s += __shfl_xor_sync(~0u, s, 8);
            s += __shfl_xor_sync(~0u, s, 16);
            if ((lane >> 2) == 0) cs[wm * 128 + c_loc] = s;
        }
    }
    __syncthreads();

    // final writes
    if (tid < 128) {
        int r = tid;
        float m = fmaxf(rm[r], rm[128 + r]);
        float h = fmaxf(rh[r], rh[128 + r]);
        float s = rs[r] + rs[128 + r];
        int rg = by * 128 + r;
        g_rowMax[bx * BB + rg] = m;
        g_rowSum[bx * BB + rg] = s;
        g_rowHn [bx * BB + rg] = h;
    } else {
        int c = tid - 128;
        float m = fmaxf(fmaxf(cm[c], cm[128 + c]), fmaxf(cm[256 + c], cm[384 + c]));
        float h = fmaxf(fmaxf(ch[c], ch[128 + c]), fmaxf(ch[256 + c], ch[384 + c]));
        float s = cs[c] + cs[128 + c] + cs[256 + c] + cs[384 + c];
        int cg = bx * 128 + c;
        g_colMax[by * BB + cg] = m;
        g_colSum[by * BB + cg] = s;
        g_colHn [by * BB + cg] = h;
    }
}

// ------------------------- kernel 3: merge partials -> loss; last block finalizes --------
__global__ void combine_kernel(float* __restrict__ out) {
    int i = blockIdx.x * blockDim.x + threadIdx.x;  // 0 .. 2*BB-1
    int idx = i & (BB - 1);
    const float *PM, *PS, *PH;
    if (i < BB) { PM = g_rowMax; PS = g_rowSum; PH = g_rowHn; }
    else        { PM = g_colMax; PS = g_colSum; PH = g_colHn; }

    float m = -3.4e38f, h = -3.4e38f;
#pragma unroll 8
    for (int t = 0; t < NT; t++) {
        m = fmaxf(m, PM[t * BB + idx]);
        h = fmaxf(h, PH[t * BB + idx]);
    }
    float s = 0.f;
#pragma unroll 8
    for (int t = 0; t < NT; t++)
        s += PS[t * BB + idx] * __expf(PM[t * BB + idx] - m);

    float d = g_diag[idx];
    float loss;
    if (h > 0.f) {
        float M = fmaxf(m, HNW_SCALE * h);
        float S = s * __expf(m - M) - __expf(h - M) + __expf(HNW_SCALE * h - M);
        loss = M + __logf(S) - d;
    } else {
        float dd = HNW_SCALE * d;
        float snd = s - __expf(d - m);
        float M = fmaxf(h, dd);
        float S = snd * __expf(m - M) + __expf(dd - M);
        loss = M + __logf(S) - dd;
    }

    __shared__ float red[256];
    __shared__ bool last;
    red[threadIdx.x] = loss;
    __syncthreads();
    for (int o = 128; o > 0; o >>= 1) {
        if (threadIdx.x < (unsigned)o) red[threadIdx.x] += red[threadIdx.x + o];
        __syncthreads();
    }
    if (threadIdx.x == 0) {
        g_part[blockIdx.x] = red[0];
        __threadfence();
        last = (atomicAdd(&g_ctr, 1u) == 63u);
    }
    __syncthreads();
    if (last && threadIdx.x == 0) {
        float t = 0.f;
#pragma unroll
        for (int b = 0; b < 64; b++) t += g_part[b];
        out[0] = t / (float)(2 * BB);
        g_ctr = 0;  // reset for next graph replay
    }
}

// ------------------------- launch -------------------------
extern "C" void kernel_launch(void* const* d_in, const int* in_sizes, int n_in,
                              void* d_out, int out_size) {
    const float* I = (const float*)d_in[0];
    const float* S = (const float*)d_in[1];
    float* out = (float*)d_out;

    cudaFuncSetAttribute(gemm_kernel, cudaFuncAttributeMaxDynamicSharedMemorySize, SMEM_BYTES);

    quant_kernel<<<QBLK, 256>>>(I, S);
    gemm_kernel<<<dim3(NT, NT, 1), 256, SMEM_BYTES>>>();
    combine_kernel<<<(2 * BB) / 256, 256>>>(out);
}